// round 1
// baseline (speedup 1.0000x reference)
#include <cuda_runtime.h>
#include <math.h>

// Problem constants
#define NTOK 65536      // V*T*N*TT*NN*DD = 2*2*256*4*4*4
#define FDIM 64
#define ATTD 128
// windows: Wn = T*N = 512, heads NH=4, H=32
// Sq = 128, Skv = 512, real kv rows per window = 192, halo = 320

// Scratch (device globals; no dynamic allocation allowed)
__device__ float g_q[NTOK * ATTD];
__device__ float g_k[NTOK * ATTD];
__device__ float g_v[NTOK * ATTD];
__device__ float g_o[NTOK * ATTD];
__device__ float g_tokv[NTOK * FDIM];
__device__ float g_h2[NTOK * FDIM];
__device__ float g_a1[NTOK * ATTD];

// token index: ((((v*2 + Ti)*256 + n)*4 + tt)*4 + nn)*4 + dd
// x/out layout offset (in floats) for token's 64-float feature row
__device__ __forceinline__ int xoff_of_token(int tok) {
    int dd = tok & 3;
    int nn = (tok >> 2) & 3;
    int tt = (tok >> 4) & 3;
    int n  = (tok >> 6) & 255;
    int Ti = (tok >> 14) & 1;
    int v  = (tok >> 15) & 1;
    return v * 2097152 + (Ti * 4 + tt) * 262144 + (n * 4 + nn) * 256 + dd * 64;
}

// ---------------------------------------------------------------------------
// Kernel 1: LN1 + Q/K/V projection. 32 tokens per CTA, 384 threads.
// Thread j owns one output column (j<128: q col j; 128..255: k col; 256..383: v col),
// weight column cached in 64 registers, activations broadcast from smem via LDS.128.
// ---------------------------------------------------------------------------
__global__ void __launch_bounds__(384) k_ln_qkv(
    const float* __restrict__ x,
    const float* __restrict__ ln1_s, const float* __restrict__ ln1_b,
    const float* __restrict__ Wq, const float* __restrict__ Wkv,
    const float* __restrict__ bkv)
{
    __shared__ __align__(16) float sh[32 * 68];
    const int tid = threadIdx.x;
    const int tokBase = blockIdx.x * 32;

    // weight column -> registers
    float w[64];
    float bias = 0.0f;
    {
        int j = tid;
        if (j < 128) {
            #pragma unroll
            for (int k = 0; k < 64; k++) w[k] = Wq[k * 128 + j];
        } else {
            int c = j - 128;   // kv column 0..255
            #pragma unroll
            for (int k = 0; k < 64; k++) w[k] = Wkv[k * 256 + c];
            bias = bkv[c];
        }
    }

    // cooperative load of 32 token rows (64 floats each)
    for (int e = tid; e < 32 * 64; e += 384) {
        int t = e >> 6, k = e & 63;
        sh[t * 68 + k] = x[xoff_of_token(tokBase + t) + k];
    }
    __syncthreads();

    // LayerNorm: 8 lanes per token, 32 tokens -> first 256 threads
    if (tid < 256) {
        int t = tid >> 3, s = tid & 7;
        float xs[8];
        float a = 0.0f, q2 = 0.0f;
        #pragma unroll
        for (int i = 0; i < 8; i++) {
            float vv = sh[t * 68 + s * 8 + i];
            xs[i] = vv; a += vv; q2 += vv * vv;
        }
        #pragma unroll
        for (int off = 4; off >= 1; off >>= 1) {
            a  += __shfl_xor_sync(0xffffffffu, a,  off);
            q2 += __shfl_xor_sync(0xffffffffu, q2, off);
        }
        float mean = a * (1.0f / 64.0f);
        float var  = q2 * (1.0f / 64.0f) - mean * mean;
        float rstd = rsqrtf(var + 1e-5f);
        #pragma unroll
        for (int i = 0; i < 8; i++) {
            int k = s * 8 + i;
            sh[t * 68 + k] = (xs[i] - mean) * rstd * ln1_s[k] + ln1_b[k];
        }
    }
    __syncthreads();

    // projection: 32 tokens
    float* outp;
    int col;
    if (tid < 128)       { outp = g_q; col = tid; }
    else if (tid < 256)  { outp = g_k; col = tid - 128; }
    else                 { outp = g_v; col = tid - 256; }

    for (int t = 0; t < 32; t++) {
        const float4* hp = (const float4*)(sh + t * 68);
        float a0 = bias, a1 = 0.0f, a2 = 0.0f, a3 = 0.0f;
        #pragma unroll
        for (int u = 0; u < 16; u++) {
            float4 h4 = hp[u];
            a0 = fmaf(h4.x, w[4 * u + 0], a0);
            a1 = fmaf(h4.y, w[4 * u + 1], a1);
            a2 = fmaf(h4.z, w[4 * u + 2], a2);
            a3 = fmaf(h4.w, w[4 * u + 3], a3);
        }
        outp[(tokBase + t) * 128 + col] = (a0 + a1) + (a2 + a3);
    }
}

// ---------------------------------------------------------------------------
// Kernel 2: windowed attention. One CTA per (window, head) = 2048 CTAs,
// 128 threads = 128 query rows. Flash-style online softmax over 192 real KV
// rows (chunks of 16 in smem) + one constant halo column with multiplicity 320.
// ---------------------------------------------------------------------------
__global__ void __launch_bounds__(128) k_attn(const float* __restrict__ bkv)
{
    __shared__ __align__(16) float sk[16 * 32];
    __shared__ __align__(16) float sv[16 * 32];
    __shared__ __align__(16) float skh[32];
    __shared__ __align__(16) float svh[32];

    const int bid = blockIdx.x;
    const int hh = bid & 3;
    const int w  = bid >> 2;
    const int Ti = w >> 8;     // window time index (0..1)
    const int n  = w & 255;    // window N index
    const int tid = threadIdx.x;

    if (tid < 32) {
        skh[tid] = bkv[hh * 32 + tid];
        svh[tid] = bkv[128 + hh * 32 + tid];
    }

    // query row for this thread: sq flattens (v, tt, nn, dd)
    const int sq = tid;
    const int qdd = sq & 3, qnn = (sq >> 2) & 3, qtt = (sq >> 4) & 3, qv2 = sq >> 6;
    const int tokQ = ((((qv2 * 2 + Ti) * 256 + n) * 4 + qtt) * 4 + qnn) * 4 + qdd;

    float4 qv[8];
    {
        const float4* qp = (const float4*)(g_q + tokQ * 128 + hh * 32);
        #pragma unroll
        for (int u = 0; u < 8; u++) qv[u] = qp[u];
    }

    const int lo = (Ti > 0) ? 2 : 0;
    const int hi = (Ti < 1) ? 2 : 0;
    const int vt = 4 + lo + hi;            // valid tt2 slots
    const int nReal = 2 * vt * 16;         // V * vt * NN * DD
    const int nHalo = 512 - nReal;
    const float scale = 0.17677669529663687f;  // 1/sqrt(32)

    float m = -1e30f;
    float l = 0.0f;
    float acc[32];
    #pragma unroll
    for (int h = 0; h < 32; h++) acc[h] = 0.0f;

    for (int r0 = 0; r0 < nReal; r0 += 16) {
        __syncthreads();
        // load chunk: thread i -> row rl = i/8, float4 u = i%8
        {
            int rl = tid >> 3;
            int u  = tid & 7;
            int r  = r0 + rl;
            if (r < nReal) {
                int rdd = r & 3, rnn = (r >> 2) & 3;
                int rt = r >> 4;
                int tsel = rt % vt;
                int v2 = rt / vt;
                int Tsrc, rtt;
                if (tsel < lo)            { Tsrc = Ti - 1; rtt = 2 + tsel; }
                else if (tsel < lo + 4)   { Tsrc = Ti;     rtt = tsel - lo; }
                else                      { Tsrc = Ti + 1; rtt = tsel - lo - 4; }
                int tokR = ((((v2 * 2 + Tsrc) * 256 + n) * 4 + rtt) * 4 + rnn) * 4 + rdd;
                const float4* kp4 = (const float4*)(g_k + tokR * 128 + hh * 32);
                const float4* vp4 = (const float4*)(g_v + tokR * 128 + hh * 32);
                ((float4*)sk)[rl * 8 + u] = kp4[u];
                ((float4*)sv)[rl * 8 + u] = vp4[u];
            }
        }
        __syncthreads();

        const int rows = min(16, nReal - r0);
        float sreg[16];
        float cmax = -1e30f;
        #pragma unroll
        for (int r = 0; r < 16; r++) {
            float s;
            if (r < rows) {
                const float4* kp = (const float4*)(sk + r * 32);
                float s0 = 0.0f, s1 = 0.0f, s2 = 0.0f, s3 = 0.0f;
                #pragma unroll
                for (int u = 0; u < 8; u++) {
                    float4 kk = kp[u];
                    s0 = fmaf(qv[u].x, kk.x, s0);
                    s1 = fmaf(qv[u].y, kk.y, s1);
                    s2 = fmaf(qv[u].z, kk.z, s2);
                    s3 = fmaf(qv[u].w, kk.w, s3);
                }
                s = ((s0 + s1) + (s2 + s3)) * scale;
            } else {
                s = -1e30f;
            }
            sreg[r] = s;
            cmax = fmaxf(cmax, s);
        }
        float mnew = fmaxf(m, cmax);
        float corr = __expf(m - mnew);
        l *= corr;
        #pragma unroll
        for (int h = 0; h < 32; h++) acc[h] *= corr;
        #pragma unroll
        for (int r = 0; r < 16; r++) {
            if (r < rows) {
                float p = __expf(sreg[r] - mnew);
                l += p;
                const float4* vp = (const float4*)(sv + r * 32);
                #pragma unroll
                for (int u = 0; u < 8; u++) {
                    float4 vvv = vp[u];
                    acc[4 * u + 0] = fmaf(p, vvv.x, acc[4 * u + 0]);
                    acc[4 * u + 1] = fmaf(p, vvv.y, acc[4 * u + 1]);
                    acc[4 * u + 2] = fmaf(p, vvv.z, acc[4 * u + 2]);
                    acc[4 * u + 3] = fmaf(p, vvv.w, acc[4 * u + 3]);
                }
            }
        }
        m = mnew;
    }

    // halo column (constant k = bkv[:128] slice, v = bkv[128:] slice), multiplicity nHalo
    {
        const float4* kp = (const float4*)skh;
        float s0 = 0.0f, s1 = 0.0f, s2 = 0.0f, s3 = 0.0f;
        #pragma unroll
        for (int u = 0; u < 8; u++) {
            float4 kk = kp[u];
            s0 = fmaf(qv[u].x, kk.x, s0);
            s1 = fmaf(qv[u].y, kk.y, s1);
            s2 = fmaf(qv[u].z, kk.z, s2);
            s3 = fmaf(qv[u].w, kk.w, s3);
        }
        float s = ((s0 + s1) + (s2 + s3)) * scale;
        float mnew = fmaxf(m, s);
        float corr = __expf(m - mnew);
        float p = __expf(s - mnew) * (float)nHalo;
        l = l * corr + p;
        const float4* vp = (const float4*)svh;
        #pragma unroll
        for (int u = 0; u < 8; u++) {
            float4 vvv = vp[u];
            acc[4 * u + 0] = acc[4 * u + 0] * corr + p * vvv.x;
            acc[4 * u + 1] = acc[4 * u + 1] * corr + p * vvv.y;
            acc[4 * u + 2] = acc[4 * u + 2] * corr + p * vvv.z;
            acc[4 * u + 3] = acc[4 * u + 3] * corr + p * vvv.w;
        }
    }

    const float inv = 1.0f / l;
    float4* op = (float4*)(g_o + tokQ * 128 + hh * 32);
    #pragma unroll
    for (int u = 0; u < 8; u++) {
        op[u] = make_float4(acc[4 * u + 0] * inv, acc[4 * u + 1] * inv,
                            acc[4 * u + 2] * inv, acc[4 * u + 3] * inv);
    }
}

// ---------------------------------------------------------------------------
// Kernel 3a: upd = o @ Wo + bo; tokv = x + gamma*upd; h2 = LN2(tokv)
// 16 tokens per CTA, 256 threads = 64 cols x 4 token-groups. Wo column in regs.
// ---------------------------------------------------------------------------
__global__ void __launch_bounds__(256) k_wo_ln2(
    const float* __restrict__ x,
    const float* __restrict__ Wo, const float* __restrict__ bo,
    const float* __restrict__ gamma,
    const float* __restrict__ ln2_s, const float* __restrict__ ln2_b)
{
    __shared__ __align__(16) float so[16 * 132];
    __shared__ __align__(16) float stok[16 * 68];
    const int tid = threadIdx.x;
    const int tokBase = blockIdx.x * 16;
    const int j = tid & 63;
    const int g = tid >> 6;

    float w[128];
    #pragma unroll
    for (int k = 0; k < 128; k++) w[k] = Wo[k * 64 + j];

    for (int e = tid; e < 16 * 128; e += 256) {
        int t = e >> 7, k = e & 127;
        so[t * 132 + k] = g_o[(tokBase + t) * 128 + k];
    }
    __syncthreads();

    const float bj = bo[j], gj = gamma[j];
    for (int t = g; t < 16; t += 4) {
        const float4* op = (const float4*)(so + t * 132);
        float a0 = bj, a1 = 0.0f, a2 = 0.0f, a3 = 0.0f;
        #pragma unroll
        for (int u = 0; u < 32; u++) {
            float4 o4 = op[u];
            a0 = fmaf(o4.x, w[4 * u + 0], a0);
            a1 = fmaf(o4.y, w[4 * u + 1], a1);
            a2 = fmaf(o4.z, w[4 * u + 2], a2);
            a3 = fmaf(o4.w, w[4 * u + 3], a3);
        }
        float upd = (a0 + a1) + (a2 + a3);
        int tok = tokBase + t;
        float tv = x[xoff_of_token(tok) + j] + gj * upd;
        stok[t * 68 + j] = tv;
        g_tokv[tok * 64 + j] = tv;
    }
    __syncthreads();

    if (tid < 128) {
        int t = tid >> 3, s = tid & 7;
        float xs[8];
        float a = 0.0f, q2 = 0.0f;
        #pragma unroll
        for (int i = 0; i < 8; i++) {
            float vv = stok[t * 68 + s * 8 + i];
            xs[i] = vv; a += vv; q2 += vv * vv;
        }
        #pragma unroll
        for (int off = 4; off >= 1; off >>= 1) {
            a  += __shfl_xor_sync(0xffffffffu, a,  off);
            q2 += __shfl_xor_sync(0xffffffffu, q2, off);
        }
        float mean = a * (1.0f / 64.0f);
        float rstd = rsqrtf(q2 * (1.0f / 64.0f) - mean * mean + 1e-5f);
        int tok = tokBase + t;
        #pragma unroll
        for (int i = 0; i < 8; i++) {
            int k = s * 8 + i;
            g_h2[tok * 64 + k] = (xs[i] - mean) * rstd * ln2_s[k] + ln2_b[k];
        }
    }
}

// ---------------------------------------------------------------------------
// Kernel 3b: a1 = gelu(h2 @ W1 + b1). 256 threads = 128 cols x 2 groups.
// ---------------------------------------------------------------------------
__global__ void __launch_bounds__(256) k_mlp1(
    const float* __restrict__ W1, const float* __restrict__ b1)
{
    __shared__ __align__(16) float sh2[16 * 68];
    const int tid = threadIdx.x;
    const int tokBase = blockIdx.x * 16;
    const int j = tid & 127;
    const int g = tid >> 7;

    float w[64];
    #pragma unroll
    for (int k = 0; k < 64; k++) w[k] = W1[k * 128 + j];

    for (int e = tid; e < 16 * 64; e += 256) {
        int t = e >> 6, k = e & 63;
        sh2[t * 68 + k] = g_h2[(tokBase + t) * 64 + k];
    }
    __syncthreads();

    const float bj = b1[j];
    for (int t = g; t < 16; t += 2) {
        const float4* hp = (const float4*)(sh2 + t * 68);
        float a0 = bj, a1a = 0.0f, a2 = 0.0f, a3 = 0.0f;
        #pragma unroll
        for (int u = 0; u < 16; u++) {
            float4 h4 = hp[u];
            a0  = fmaf(h4.x, w[4 * u + 0], a0);
            a1a = fmaf(h4.y, w[4 * u + 1], a1a);
            a2  = fmaf(h4.z, w[4 * u + 2], a2);
            a3  = fmaf(h4.w, w[4 * u + 3], a3);
        }
        float uu = (a0 + a1a) + (a2 + a3);
        // jax.nn.gelu approximate=True
        float inner = 0.7978845608028654f * (uu + 0.044715f * uu * uu * uu);
        float gv = 0.5f * uu * (1.0f + tanhf(inner));
        g_a1[(tokBase + t) * 128 + j] = gv;
    }
}

// ---------------------------------------------------------------------------
// Kernel 3c: out = tokv + gamma_mlp * (a1 @ W2 + b2), written in x layout.
// 256 threads = 64 cols x 4 groups.
// ---------------------------------------------------------------------------
__global__ void __launch_bounds__(256) k_mlp2(
    const float* __restrict__ W2, const float* __restrict__ b2,
    const float* __restrict__ gamma_mlp, float* __restrict__ out)
{
    __shared__ __align__(16) float sa[16 * 132];
    const int tid = threadIdx.x;
    const int tokBase = blockIdx.x * 16;
    const int j = tid & 63;
    const int g = tid >> 6;

    float w[128];
    #pragma unroll
    for (int k = 0; k < 128; k++) w[k] = W2[k * 64 + j];

    for (int e = tid; e < 16 * 128; e += 256) {
        int t = e >> 7, k = e & 127;
        sa[t * 132 + k] = g_a1[(tokBase + t) * 128 + k];
    }
    __syncthreads();

    const float bj = b2[j], gj = gamma_mlp[j];
    for (int t = g; t < 16; t += 4) {
        const float4* ap = (const float4*)(sa + t * 132);
        float a0 = bj, a1 = 0.0f, a2 = 0.0f, a3 = 0.0f;
        #pragma unroll
        for (int u = 0; u < 32; u++) {
            float4 a4 = ap[u];
            a0 = fmaf(a4.x, w[4 * u + 0], a0);
            a1 = fmaf(a4.y, w[4 * u + 1], a1);
            a2 = fmaf(a4.z, w[4 * u + 2], a2);
            a3 = fmaf(a4.w, w[4 * u + 3], a3);
        }
        float mlp = (a0 + a1) + (a2 + a3);
        int tok = tokBase + t;
        out[xoff_of_token(tok) + j] = g_tokv[tok * 64 + j] + gj * mlp;
    }
}

// ---------------------------------------------------------------------------
extern "C" void kernel_launch(void* const* d_in, const int* in_sizes, int n_in,
                              void* d_out, int out_size)
{
    (void)in_sizes; (void)n_in; (void)out_size;
    const float* x         = (const float*)d_in[0];
    const float* ln1_s     = (const float*)d_in[1];
    const float* ln1_b     = (const float*)d_in[2];
    const float* Wq        = (const float*)d_in[3];
    const float* Wkv       = (const float*)d_in[4];
    const float* bkv       = (const float*)d_in[5];
    const float* Wo        = (const float*)d_in[6];
    const float* bo        = (const float*)d_in[7];
    const float* gamma     = (const float*)d_in[8];
    const float* ln2_s     = (const float*)d_in[9];
    const float* ln2_b     = (const float*)d_in[10];
    const float* W1        = (const float*)d_in[11];
    const float* b1        = (const float*)d_in[12];
    const float* W2        = (const float*)d_in[13];
    const float* b2        = (const float*)d_in[14];
    const float* gamma_mlp = (const float*)d_in[15];
    float* out = (float*)d_out;

    k_ln_qkv<<<NTOK / 32, 384>>>(x, ln1_s, ln1_b, Wq, Wkv, bkv);
    k_attn<<<512 * 4, 128>>>(bkv);
    k_wo_ln2<<<NTOK / 16, 256>>>(x, Wo, bo, gamma, ln2_s, ln2_b);
    k_mlp1<<<NTOK / 16, 256>>>(W1, b1);
    k_mlp2<<<NTOK / 16, 256>>>(W2, b2, gamma_mlp, out);
}

// round 2
// speedup vs baseline: 4.8894x; 4.8894x over previous
#include <cuda_runtime.h>
#include <cuda_bf16.h>
#include <math.h>

#define NTOK 65536
#define SCALE 0.17677669529663687f   // 1/sqrt(32), folded into q

// ---------------- device scratch (bf16 activations) ----------------
__device__ __nv_bfloat16 g_q[NTOK * 128];
__device__ __nv_bfloat16 g_k[NTOK * 128];
__device__ __nv_bfloat16 g_v[NTOK * 128];
__device__ __nv_bfloat16 g_o[NTOK * 128];
// bf16 weights, [n][k] row-major
__device__ __nv_bfloat16 Wqkv_b[384 * 64];
__device__ __nv_bfloat16 Wo_b[64 * 128];
__device__ __nv_bfloat16 W1_b[128 * 64];
__device__ __nv_bfloat16 W2_b[64 * 128];

// token index: ((((v*2 + Ti)*256 + n)*4 + tt)*4 + nn)*4 + dd
__device__ __forceinline__ int xoff_of_token(int tok) {
    int dd = tok & 3;
    int nn = (tok >> 2) & 3;
    int tt = (tok >> 4) & 3;
    int n  = (tok >> 6) & 255;
    int Ti = (tok >> 14) & 1;
    int v  = (tok >> 15) & 1;
    return v * 2097152 + (Ti * 4 + tt) * 262144 + (n * 4 + nn) * 256 + dd * 64;
}

// attention: q-row (0..127) within window (Ti,n) -> token
__device__ __forceinline__ int tok_of_qrow(int row, int Ti, int n) {
    int dd = row & 3, nn = (row >> 2) & 3, tt = (row >> 4) & 3, v2 = row >> 6;
    return ((((v2 * 2 + Ti) * 256 + n) * 4 + tt) * 4 + nn) * 4 + dd;
}

__device__ __forceinline__ unsigned pack_bf2(float lo, float hi) {
    unsigned ulo = (unsigned)__bfloat16_as_ushort(__float2bfloat16(lo));
    unsigned uhi = (unsigned)__bfloat16_as_ushort(__float2bfloat16(hi));
    return (uhi << 16) | ulo;
}
__device__ __forceinline__ float bf_lo(unsigned u) {
    return __bfloat162float(__ushort_as_bfloat16((unsigned short)(u & 0xffff)));
}
__device__ __forceinline__ float bf_hi(unsigned u) {
    return __bfloat162float(__ushort_as_bfloat16((unsigned short)(u >> 16)));
}

__device__ __forceinline__ void mma16816(float c[4], const unsigned a[4], unsigned b0, unsigned b1) {
    asm volatile(
        "mma.sync.aligned.m16n8k16.row.col.f32.bf16.bf16.f32 "
        "{%0,%1,%2,%3}, {%4,%5,%6,%7}, {%8,%9}, {%0,%1,%2,%3};"
        : "+f"(c[0]), "+f"(c[1]), "+f"(c[2]), "+f"(c[3])
        : "r"(a[0]), "r"(a[1]), "r"(a[2]), "r"(a[3]), "r"(b0), "r"(b1));
}

// ---------------------------------------------------------------------------
// k_cvt: f32 weights -> bf16 [n][k] device arrays
// ---------------------------------------------------------------------------
__global__ void k_cvt(const float* __restrict__ Wq, const float* __restrict__ Wkv,
                      const float* __restrict__ Wo, const float* __restrict__ W1,
                      const float* __restrict__ W2)
{
    int i = blockIdx.x * 256 + threadIdx.x;
    if (i < 24576) {
        int nn = i >> 6, kk = i & 63;
        float v = (nn < 128) ? Wq[kk * 128 + nn] : Wkv[kk * 256 + (nn - 128)];
        Wqkv_b[i] = __float2bfloat16(v);
    } else if (i < 32768) {
        int j = i - 24576; int nn = j >> 7, kk = j & 127;
        Wo_b[j] = __float2bfloat16(Wo[kk * 64 + nn]);
    } else if (i < 40960) {
        int j = i - 32768; int nn = j >> 6, kk = j & 63;
        W1_b[j] = __float2bfloat16(W1[kk * 128 + nn]);
    } else if (i < 49152) {
        int j = i - 40960; int nn = j >> 7, kk = j & 127;
        W2_b[j] = __float2bfloat16(W2[kk * 64 + nn]);
    }
}

// ---------------------------------------------------------------------------
// k1: LN1 (fp32) + QKV projection via bf16 mma. 64 tokens/CTA, 256 threads.
// 8 warps = 2 Mwarps x 4 Nwarps. Warp tile: M=32 (2 m16), N=96 (12 n8), K=64.
// q written with SCALE folded in.
// ---------------------------------------------------------------------------
__global__ void __launch_bounds__(256) k1_ln_qkv(
    const float* __restrict__ x,
    const float* __restrict__ ln1_s, const float* __restrict__ ln1_b,
    const float* __restrict__ bkv)
{
    __shared__ unsigned sA[64 * 36];    // 64 rows x 72 bf16 (64 + pad)
    const int tid = threadIdx.x;
    const int tokBase = blockIdx.x * 64;

    // --- LN1: 4 lanes per row, 16 elems each ---
    {
        int row = tid >> 2, s = tid & 3;
        const float* xr = x + xoff_of_token(tokBase + row);
        float h[16];
        #pragma unroll
        for (int j = 0; j < 4; j++) {
            float4 xv = *(const float4*)(xr + s * 16 + j * 4);
            h[4 * j + 0] = xv.x; h[4 * j + 1] = xv.y; h[4 * j + 2] = xv.z; h[4 * j + 3] = xv.w;
        }
        float a = 0.0f, q2 = 0.0f;
        #pragma unroll
        for (int j = 0; j < 16; j++) { a += h[j]; q2 += h[j] * h[j]; }
        a  += __shfl_xor_sync(0xffffffffu, a, 1);  a  += __shfl_xor_sync(0xffffffffu, a, 2);
        q2 += __shfl_xor_sync(0xffffffffu, q2, 1); q2 += __shfl_xor_sync(0xffffffffu, q2, 2);
        float mean = a * (1.0f / 64.0f);
        float rstd = rsqrtf(q2 * (1.0f / 64.0f) - mean * mean + 1e-5f);
        float hn[16];
        #pragma unroll
        for (int j = 0; j < 16; j++) {
            int k = s * 16 + j;
            hn[j] = (h[j] - mean) * rstd * ln1_s[k] + ln1_b[k];
        }
        #pragma unroll
        for (int j = 0; j < 8; j++)
            sA[row * 36 + s * 8 + j] = pack_bf2(hn[2 * j], hn[2 * j + 1]);
    }
    __syncthreads();

    // --- GEMM ---
    const int wq = tid >> 5, lane = tid & 31;
    const int mw = wq >> 2, nw = wq & 3;
    const int g = lane >> 2, t = lane & 3;

    unsigned a[2][4][4];
    #pragma unroll
    for (int mt = 0; mt < 2; mt++) {
        int r0 = mw * 32 + mt * 16 + g;
        #pragma unroll
        for (int kc = 0; kc < 4; kc++) {
            a[mt][kc][0] = sA[r0 * 36 + kc * 8 + t];
            a[mt][kc][1] = sA[(r0 + 8) * 36 + kc * 8 + t];
            a[mt][kc][2] = sA[r0 * 36 + kc * 8 + t + 4];
            a[mt][kc][3] = sA[(r0 + 8) * 36 + kc * 8 + t + 4];
        }
    }

    const unsigned* Wu = (const unsigned*)Wqkv_b;
    unsigned* qg = (unsigned*)g_q;
    unsigned* kg = (unsigned*)g_k;
    unsigned* vg = (unsigned*)g_v;

    #pragma unroll
    for (int nt = 0; nt < 12; nt++) {
        float acc0[4] = {0, 0, 0, 0}, acc1[4] = {0, 0, 0, 0};
        int nb = nw * 96 + nt * 8 + g;
        #pragma unroll
        for (int kc = 0; kc < 4; kc++) {
            unsigned b0 = Wu[nb * 32 + kc * 8 + t];
            unsigned b1 = Wu[nb * 32 + kc * 8 + t + 4];
            mma16816(acc0, a[0][kc], b0, b1);
            mma16816(acc1, a[1][kc], b0, b1);
        }
        int n0 = nw * 96 + nt * 8 + 2 * t;     // even col
        #pragma unroll
        for (int mt = 0; mt < 2; mt++) {
            float* c = (mt == 0) ? acc0 : acc1;
            int r0 = mw * 32 + mt * 16 + g;
            int tok0 = tokBase + r0, tok1 = tokBase + r0 + 8;
            if (n0 < 128) {
                qg[tok0 * 64 + n0 / 2] = pack_bf2(c[0] * SCALE, c[1] * SCALE);
                qg[tok1 * 64 + n0 / 2] = pack_bf2(c[2] * SCALE, c[3] * SCALE);
            } else if (n0 < 256) {
                float bb0 = bkv[n0 - 128], bb1 = bkv[n0 - 127];
                kg[tok0 * 64 + (n0 - 128) / 2] = pack_bf2(c[0] + bb0, c[1] + bb1);
                kg[tok1 * 64 + (n0 - 128) / 2] = pack_bf2(c[2] + bb0, c[3] + bb1);
            } else {
                float bb0 = bkv[n0 - 128], bb1 = bkv[n0 - 127];
                vg[tok0 * 64 + (n0 - 256) / 2] = pack_bf2(c[0] + bb0, c[1] + bb1);
                vg[tok1 * 64 + (n0 - 256) / 2] = pack_bf2(c[2] + bb0, c[3] + bb1);
            }
        }
    }
}

// ---------------------------------------------------------------------------
// k2: flash attention on tensor cores. CTA = (window, head): 2048 CTAs,
// 128 threads (4 warps x 32 q rows). 12 chunks of 16 real kv rows + constant
// halo column with multiplicity 320.
// ---------------------------------------------------------------------------
__global__ void __launch_bounds__(128) k2_attn(const float* __restrict__ bkv)
{
    __shared__ unsigned sk_u[16 * 18];       // K chunk: 16 rows x 36 bf16 (32 + pad)
    __shared__ __nv_bfloat16 svT[32 * 18];   // V chunk transposed: [col][row], stride 18
    __shared__ float kh[32], vh[32];

    const int bid = blockIdx.x;
    const int hh = bid & 3;
    const int w  = bid >> 2;
    const int Ti = w >> 8;
    const int n  = w & 255;
    const int tid = threadIdx.x;
    const int wid = tid >> 5, lane = tid & 31;
    const int g = lane >> 2, t = lane & 3;

    if (tid < 32) {
        kh[tid] = bkv[hh * 32 + tid];
        vh[tid] = bkv[128 + hh * 32 + tid];
    }

    // q fragments (scale already folded in)
    const unsigned* qg = (const unsigned*)g_q;
    unsigned qa[2][2][4];
    int tokR0[2], tokR1[2];
    #pragma unroll
    for (int mt = 0; mt < 2; mt++) {
        int r0 = wid * 32 + mt * 16 + g;
        tokR0[mt] = tok_of_qrow(r0, Ti, n);
        tokR1[mt] = tok_of_qrow(r0 + 8, Ti, n);
        int b0 = tokR0[mt] * 64 + hh * 16;
        int b1 = tokR1[mt] * 64 + hh * 16;
        #pragma unroll
        for (int kc = 0; kc < 2; kc++) {
            qa[mt][kc][0] = qg[b0 + kc * 8 + t];
            qa[mt][kc][1] = qg[b1 + kc * 8 + t];
            qa[mt][kc][2] = qg[b0 + kc * 8 + t + 4];
            qa[mt][kc][3] = qg[b1 + kc * 8 + t + 4];
        }
    }

    float m0[2] = {-1e30f, -1e30f}, m1[2] = {-1e30f, -1e30f};
    float l0[2] = {0.0f, 0.0f},    l1[2] = {0.0f, 0.0f};
    float acc[2][4][4];
    #pragma unroll
    for (int mt = 0; mt < 2; mt++)
        #pragma unroll
        for (int ot = 0; ot < 4; ot++)
            #pragma unroll
            for (int e = 0; e < 4; e++) acc[mt][ot][e] = 0.0f;

    const int lo = (Ti > 0) ? 2 : 0;
    const unsigned* kgm = (const unsigned*)g_k;
    const unsigned* vgm = (const unsigned*)g_v;
    const unsigned* svu = (const unsigned*)svT;

    for (int c = 0; c < 12; c++) {
        __syncthreads();
        {
            int rl = tid >> 3, u = tid & 7;
            int r = c * 16 + rl;
            int rdd = r & 3, rnn = (r >> 2) & 3, rt = r >> 4;
            int tsel = rt % 6, v2 = rt / 6;
            int Tsrc, rtt;
            if (tsel < lo)            { Tsrc = Ti - 1; rtt = 2 + tsel; }
            else if (tsel < lo + 4)   { Tsrc = Ti;     rtt = tsel - lo; }
            else                      { Tsrc = Ti + 1; rtt = tsel - lo - 4; }
            int tokR = ((((v2 * 2 + Tsrc) * 256 + n) * 4 + rtt) * 4 + rnn) * 4 + rdd;
            int base = tokR * 64 + hh * 16;
            sk_u[rl * 18 + 2 * u]     = kgm[base + 2 * u];
            sk_u[rl * 18 + 2 * u + 1] = kgm[base + 2 * u + 1];
            unsigned v0 = vgm[base + 2 * u], v1 = vgm[base + 2 * u + 1];
            svT[(4 * u + 0) * 18 + rl] = __ushort_as_bfloat16((unsigned short)(v0 & 0xffff));
            svT[(4 * u + 1) * 18 + rl] = __ushort_as_bfloat16((unsigned short)(v0 >> 16));
            svT[(4 * u + 2) * 18 + rl] = __ushort_as_bfloat16((unsigned short)(v1 & 0xffff));
            svT[(4 * u + 3) * 18 + rl] = __ushort_as_bfloat16((unsigned short)(v1 >> 16));
        }
        __syncthreads();

        unsigned kb[2][2][2];
        #pragma unroll
        for (int nt = 0; nt < 2; nt++)
            #pragma unroll
            for (int kc = 0; kc < 2; kc++) {
                kb[nt][kc][0] = sk_u[(nt * 8 + g) * 18 + kc * 8 + t];
                kb[nt][kc][1] = sk_u[(nt * 8 + g) * 18 + kc * 8 + t + 4];
            }
        unsigned vb[4][2];
        #pragma unroll
        for (int ot = 0; ot < 4; ot++) {
            vb[ot][0] = svu[(ot * 8 + g) * 9 + t];
            vb[ot][1] = svu[(ot * 8 + g) * 9 + t + 4];
        }

        #pragma unroll
        for (int mt = 0; mt < 2; mt++) {
            float s0[4] = {0, 0, 0, 0}, s1[4] = {0, 0, 0, 0};
            mma16816(s0, qa[mt][0], kb[0][0][0], kb[0][0][1]);
            mma16816(s0, qa[mt][1], kb[0][1][0], kb[0][1][1]);
            mma16816(s1, qa[mt][0], kb[1][0][0], kb[1][0][1]);
            mma16816(s1, qa[mt][1], kb[1][1][0], kb[1][1][1]);

            // online softmax (rows g and g+8)
            float rmax0 = fmaxf(fmaxf(s0[0], s0[1]), fmaxf(s1[0], s1[1]));
            float rmax1 = fmaxf(fmaxf(s0[2], s0[3]), fmaxf(s1[2], s1[3]));
            rmax0 = fmaxf(rmax0, __shfl_xor_sync(0xffffffffu, rmax0, 1));
            rmax0 = fmaxf(rmax0, __shfl_xor_sync(0xffffffffu, rmax0, 2));
            rmax1 = fmaxf(rmax1, __shfl_xor_sync(0xffffffffu, rmax1, 1));
            rmax1 = fmaxf(rmax1, __shfl_xor_sync(0xffffffffu, rmax1, 2));
            float mn0 = fmaxf(m0[mt], rmax0), mn1 = fmaxf(m1[mt], rmax1);
            float cr0 = __expf(m0[mt] - mn0), cr1 = __expf(m1[mt] - mn1);
            float p00 = __expf(s0[0] - mn0), p01 = __expf(s0[1] - mn0);
            float p10 = __expf(s1[0] - mn0), p11 = __expf(s1[1] - mn0);
            float q00 = __expf(s0[2] - mn1), q01 = __expf(s0[3] - mn1);
            float q10 = __expf(s1[2] - mn1), q11 = __expf(s1[3] - mn1);
            float ps0 = p00 + p01 + p10 + p11;
            float ps1 = q00 + q01 + q10 + q11;
            ps0 += __shfl_xor_sync(0xffffffffu, ps0, 1);
            ps0 += __shfl_xor_sync(0xffffffffu, ps0, 2);
            ps1 += __shfl_xor_sync(0xffffffffu, ps1, 1);
            ps1 += __shfl_xor_sync(0xffffffffu, ps1, 2);
            l0[mt] = l0[mt] * cr0 + ps0;
            l1[mt] = l1[mt] * cr1 + ps1;
            m0[mt] = mn0; m1[mt] = mn1;

            unsigned pa[4];
            pa[0] = pack_bf2(p00, p01);
            pa[1] = pack_bf2(q00, q01);
            pa[2] = pack_bf2(p10, p11);
            pa[3] = pack_bf2(q10, q11);

            #pragma unroll
            for (int ot = 0; ot < 4; ot++) {
                acc[mt][ot][0] *= cr0; acc[mt][ot][1] *= cr0;
                acc[mt][ot][2] *= cr1; acc[mt][ot][3] *= cr1;
                mma16816(acc[mt][ot], pa, vb[ot][0], vb[ot][1]);
            }
        }
    }

    // --- constant halo column, multiplicity 320 ---
    #pragma unroll
    for (int mt = 0; mt < 2; mt++) {
        float hd0 = 0.0f, hd1 = 0.0f;
        #pragma unroll
        for (int kc = 0; kc < 2; kc++) {
            int kb0 = kc * 16 + 2 * t;
            hd0 += bf_lo(qa[mt][kc][0]) * kh[kb0]     + bf_hi(qa[mt][kc][0]) * kh[kb0 + 1];
            hd0 += bf_lo(qa[mt][kc][2]) * kh[kb0 + 8] + bf_hi(qa[mt][kc][2]) * kh[kb0 + 9];
            hd1 += bf_lo(qa[mt][kc][1]) * kh[kb0]     + bf_hi(qa[mt][kc][1]) * kh[kb0 + 1];
            hd1 += bf_lo(qa[mt][kc][3]) * kh[kb0 + 8] + bf_hi(qa[mt][kc][3]) * kh[kb0 + 9];
        }
        hd0 += __shfl_xor_sync(0xffffffffu, hd0, 1);
        hd0 += __shfl_xor_sync(0xffffffffu, hd0, 2);
        hd1 += __shfl_xor_sync(0xffffffffu, hd1, 1);
        hd1 += __shfl_xor_sync(0xffffffffu, hd1, 2);
        float mn0 = fmaxf(m0[mt], hd0), mn1 = fmaxf(m1[mt], hd1);
        float cr0 = __expf(m0[mt] - mn0), cr1 = __expf(m1[mt] - mn1);
        float ph0 = __expf(hd0 - mn0) * 320.0f;
        float ph1 = __expf(hd1 - mn1) * 320.0f;
        l0[mt] = l0[mt] * cr0 + ph0;
        l1[mt] = l1[mt] * cr1 + ph1;
        #pragma unroll
        for (int ot = 0; ot < 4; ot++) {
            int c0 = ot * 8 + 2 * t;
            acc[mt][ot][0] = acc[mt][ot][0] * cr0 + ph0 * vh[c0];
            acc[mt][ot][1] = acc[mt][ot][1] * cr0 + ph0 * vh[c0 + 1];
            acc[mt][ot][2] = acc[mt][ot][2] * cr1 + ph1 * vh[c0];
            acc[mt][ot][3] = acc[mt][ot][3] * cr1 + ph1 * vh[c0 + 1];
        }
    }

    // --- epilogue: o (bf16) ---
    unsigned* og = (unsigned*)g_o;
    #pragma unroll
    for (int mt = 0; mt < 2; mt++) {
        float inv0 = 1.0f / l0[mt], inv1 = 1.0f / l1[mt];
        int b0 = tokR0[mt] * 64 + hh * 16;
        int b1 = tokR1[mt] * 64 + hh * 16;
        #pragma unroll
        for (int ot = 0; ot < 4; ot++) {
            og[b0 + ot * 4 + t] = pack_bf2(acc[mt][ot][0] * inv0, acc[mt][ot][1] * inv0);
            og[b1 + ot * 4 + t] = pack_bf2(acc[mt][ot][2] * inv1, acc[mt][ot][3] * inv1);
        }
    }
}

// ---------------------------------------------------------------------------
// k3: fused Wo + residual + LN2 + MLP1 + gelu + MLP2 + residual -> out.
// 64 tokens/CTA, 256 threads = 2 Mwarps x 4 Nwarps.
// ---------------------------------------------------------------------------
__global__ void __launch_bounds__(256) k3_post(
    const float* __restrict__ x,
    const float* __restrict__ bo, const float* __restrict__ gamma,
    const float* __restrict__ ln2_s, const float* __restrict__ ln2_b,
    const float* __restrict__ b1, const float* __restrict__ b2,
    const float* __restrict__ gamma_mlp, float* __restrict__ out)
{
    __shared__ float   stok[64 * 68];     // residual tok (fp32)
    __shared__ unsigned sh2[64 * 36];     // h2 bf16, stride 72 bf16
    __shared__ unsigned sa[64 * 66];      // gelu out bf16, stride 132 bf16

    const int tid = threadIdx.x;
    const int tokBase = blockIdx.x * 64;
    const int wq = tid >> 5, lane = tid & 31;
    const int mw = wq >> 2, nw = wq & 3;
    const int g = lane >> 2, t = lane & 3;

    const unsigned* og = (const unsigned*)g_o;
    const unsigned* Wou = (const unsigned*)Wo_b;
    const unsigned* W1u = (const unsigned*)W1_b;
    const unsigned* W2u = (const unsigned*)W2_b;

    // ---- GEMM1: upd = o @ Wo ; tok = x + gamma*upd -> stok ----
    unsigned ao[2][8][4];
    int rr0[2], xo0[2], xo1[2];
    #pragma unroll
    for (int mt = 0; mt < 2; mt++) {
        int r0 = mw * 32 + mt * 16 + g;
        rr0[mt] = r0;
        int tok0 = tokBase + r0, tok1 = tok0 + 8;
        xo0[mt] = xoff_of_token(tok0);
        xo1[mt] = xoff_of_token(tok1);
        int b0 = tok0 * 64, b1 = tok1 * 64;
        #pragma unroll
        for (int kc = 0; kc < 8; kc++) {
            ao[mt][kc][0] = og[b0 + kc * 8 + t];
            ao[mt][kc][1] = og[b1 + kc * 8 + t];
            ao[mt][kc][2] = og[b0 + kc * 8 + t + 4];
            ao[mt][kc][3] = og[b1 + kc * 8 + t + 4];
        }
    }
    #pragma unroll
    for (int nt = 0; nt < 2; nt++) {
        float acc0[4] = {0, 0, 0, 0}, acc1[4] = {0, 0, 0, 0};
        int nb = nw * 16 + nt * 8 + g;
        #pragma unroll
        for (int kc = 0; kc < 8; kc++) {
            unsigned b0 = Wou[nb * 64 + kc * 8 + t];
            unsigned b1 = Wou[nb * 64 + kc * 8 + t + 4];
            mma16816(acc0, ao[0][kc], b0, b1);
            mma16816(acc1, ao[1][kc], b0, b1);
        }
        int n0 = nw * 16 + nt * 8 + 2 * t;
        float bo0 = bo[n0], bo1 = bo[n0 + 1];
        float gm0 = gamma[n0], gm1 = gamma[n0 + 1];
        #pragma unroll
        for (int mt = 0; mt < 2; mt++) {
            float* cc = (mt == 0) ? acc0 : acc1;
            int r0 = rr0[mt];
            stok[r0 * 68 + n0]           = x[xo0[mt] + n0]     + gm0 * (cc[0] + bo0);
            stok[r0 * 68 + n0 + 1]       = x[xo0[mt] + n0 + 1] + gm1 * (cc[1] + bo1);
            stok[(r0 + 8) * 68 + n0]     = x[xo1[mt] + n0]     + gm0 * (cc[2] + bo0);
            stok[(r0 + 8) * 68 + n0 + 1] = x[xo1[mt] + n0 + 1] + gm1 * (cc[3] + bo1);
        }
    }
    __syncthreads();

    // ---- LN2 -> sh2 (bf16) ----
    {
        int row = tid >> 2, s = tid & 3;
        float h[16];
        #pragma unroll
        for (int j = 0; j < 16; j++) h[j] = stok[row * 68 + s * 16 + j];
        float a = 0.0f, q2 = 0.0f;
        #pragma unroll
        for (int j = 0; j < 16; j++) { a += h[j]; q2 += h[j] * h[j]; }
        a  += __shfl_xor_sync(0xffffffffu, a, 1);  a  += __shfl_xor_sync(0xffffffffu, a, 2);
        q2 += __shfl_xor_sync(0xffffffffu, q2, 1); q2 += __shfl_xor_sync(0xffffffffu, q2, 2);
        float mean = a * (1.0f / 64.0f);
        float rstd = rsqrtf(q2 * (1.0f / 64.0f) - mean * mean + 1e-5f);
        #pragma unroll
        for (int j = 0; j < 8; j++) {
            int k = s * 16 + 2 * j;
            float h0 = (h[2 * j]     - mean) * rstd * ln2_s[k]     + ln2_b[k];
            float h1 = (h[2 * j + 1] - mean) * rstd * ln2_s[k + 1] + ln2_b[k + 1];
            sh2[row * 36 + s * 8 + j] = pack_bf2(h0, h1);
        }
    }
    __syncthreads();

    // ---- GEMM2: u = h2 @ W1 + b1 ; a = gelu(u) -> sa ----
    unsigned ah[2][4][4];
    #pragma unroll
    for (int mt = 0; mt < 2; mt++) {
        int r0 = rr0[mt];
        #pragma unroll
        for (int kc = 0; kc < 4; kc++) {
            ah[mt][kc][0] = sh2[r0 * 36 + kc * 8 + t];
            ah[mt][kc][1] = sh2[(r0 + 8) * 36 + kc * 8 + t];
            ah[mt][kc][2] = sh2[r0 * 36 + kc * 8 + t + 4];
            ah[mt][kc][3] = sh2[(r0 + 8) * 36 + kc * 8 + t + 4];
        }
    }
    #pragma unroll
    for (int nt = 0; nt < 4; nt++) {
        float acc0[4] = {0, 0, 0, 0}, acc1[4] = {0, 0, 0, 0};
        int nb = nw * 32 + nt * 8 + g;
        #pragma unroll
        for (int kc = 0; kc < 4; kc++) {
            unsigned b0 = W1u[nb * 32 + kc * 8 + t];
            unsigned b1 = W1u[nb * 32 + kc * 8 + t + 4];
            mma16816(acc0, ah[0][kc], b0, b1);
            mma16816(acc1, ah[1][kc], b0, b1);
        }
        int n0 = nw * 32 + nt * 8 + 2 * t;
        float bb0 = b1[n0], bb1 = b1[n0 + 1];
        #pragma unroll
        for (int mt = 0; mt < 2; mt++) {
            float* cc = (mt == 0) ? acc0 : acc1;
            int r0 = rr0[mt];
            #pragma unroll
            for (int half = 0; half < 2; half++) {
                float u0 = cc[2 * half]     + bb0;
                float u1 = cc[2 * half + 1] + bb1;
                float i0 = 0.7978845608028654f * (u0 + 0.044715f * u0 * u0 * u0);
                float i1 = 0.7978845608028654f * (u1 + 0.044715f * u1 * u1 * u1);
                float gv0 = 0.5f * u0 * (1.0f + tanhf(i0));
                float gv1 = 0.5f * u1 * (1.0f + tanhf(i1));
                int row = r0 + half * 8;
                sa[row * 66 + n0 / 2] = pack_bf2(gv0, gv1);
            }
        }
    }
    __syncthreads();

    // ---- GEMM3: mlp = a @ W2 + b2 ; out = tok + gamma_mlp * mlp ----
    unsigned aa[2][8][4];
    #pragma unroll
    for (int mt = 0; mt < 2; mt++) {
        int r0 = rr0[mt];
        #pragma unroll
        for (int kc = 0; kc < 8; kc++) {
            aa[mt][kc][0] = sa[r0 * 66 + kc * 8 + t];
            aa[mt][kc][1] = sa[(r0 + 8) * 66 + kc * 8 + t];
            aa[mt][kc][2] = sa[r0 * 66 + kc * 8 + t + 4];
            aa[mt][kc][3] = sa[(r0 + 8) * 66 + kc * 8 + t + 4];
        }
    }
    #pragma unroll
    for (int nt = 0; nt < 2; nt++) {
        float acc0[4] = {0, 0, 0, 0}, acc1[4] = {0, 0, 0, 0};
        int nb = nw * 16 + nt * 8 + g;
        #pragma unroll
        for (int kc = 0; kc < 8; kc++) {
            unsigned b0 = W2u[nb * 128 + kc * 8 + t];
            unsigned b1 = W2u[nb * 128 + kc * 8 + t + 4];
            mma16816(acc0, aa[0][kc], b0, b1);
            mma16816(acc1, aa[1][kc], b0, b1);
        }
        int n0 = nw * 16 + nt * 8 + 2 * t;
        float bb0 = b2[n0], bb1 = b2[n0 + 1];
        float gm0 = gamma_mlp[n0], gm1 = gamma_mlp[n0 + 1];
        #pragma unroll
        for (int mt = 0; mt < 2; mt++) {
            float* cc = (mt == 0) ? acc0 : acc1;
            int r0 = rr0[mt];
            float o00 = stok[r0 * 68 + n0]           + gm0 * (cc[0] + bb0);
            float o01 = stok[r0 * 68 + n0 + 1]       + gm1 * (cc[1] + bb1);
            float o10 = stok[(r0 + 8) * 68 + n0]     + gm0 * (cc[2] + bb0);
            float o11 = stok[(r0 + 8) * 68 + n0 + 1] + gm1 * (cc[3] + bb1);
            *(float2*)(out + xo0[mt] + n0) = make_float2(o00, o01);
            *(float2*)(out + xo1[mt] + n0) = make_float2(o10, o11);
        }
    }
}

// ---------------------------------------------------------------------------
extern "C" void kernel_launch(void* const* d_in, const int* in_sizes, int n_in,
                              void* d_out, int out_size)
{
    (void)in_sizes; (void)n_in; (void)out_size;
    const float* x         = (const float*)d_in[0];
    const float* ln1_s     = (const float*)d_in[1];
    const float* ln1_b     = (const float*)d_in[2];
    const float* Wq        = (const float*)d_in[3];
    const float* Wkv       = (const float*)d_in[4];
    const float* bkv       = (const float*)d_in[5];
    const float* Wo        = (const float*)d_in[6];
    const float* bo        = (const float*)d_in[7];
    const float* gamma     = (const float*)d_in[8];
    const float* ln2_s     = (const float*)d_in[9];
    const float* ln2_b     = (const float*)d_in[10];
    const float* W1        = (const float*)d_in[11];
    const float* b1        = (const float*)d_in[12];
    const float* W2        = (const float*)d_in[13];
    const float* b2        = (const float*)d_in[14];
    const float* gamma_mlp = (const float*)d_in[15];
    float* out = (float*)d_out;

    k_cvt<<<192, 256>>>(Wq, Wkv, Wo, W1, W2);
    k1_ln_qkv<<<NTOK / 64, 256>>>(x, ln1_s, ln1_b, bkv);
    k2_attn<<<512 * 4, 128>>>(bkv);
    k3_post<<<NTOK / 64, 256>>>(x, bo, gamma, ln2_s, ln2_b, b1, b2, gamma_mlp, out);
}

// round 3
// speedup vs baseline: 6.3866x; 1.3062x over previous
#include <cuda_runtime.h>
#include <cuda_bf16.h>
#include <math.h>

#define NTOK 65536
#define SCALE 0.17677669529663687f   // 1/sqrt(32), folded into q

// ---------------- device scratch ----------------
__device__ __nv_bfloat16 g_q[NTOK * 128];
__device__ __nv_bfloat16 g_k[NTOK * 128];
__device__ __nv_bfloat16 g_v[NTOK * 128];
__device__ __nv_bfloat16 g_o[NTOK * 128];
// weights packed in per-lane mma B-fragment order
__device__ unsigned WqkvP[12288];   // N=384, K=64  (KC=4, NT=48)
__device__ unsigned WoP[4096];      // N=64,  K=128 (KC=8, NT=8)
__device__ unsigned W1P[4096];      // N=128, K=64  (KC=4, NT=16)
__device__ unsigned W2P[4096];      // N=64,  K=128 (KC=8, NT=8)

// token index: ((((v*2 + Ti)*256 + n)*4 + tt)*4 + nn)*4 + dd
__device__ __forceinline__ int xoff_of_token(int tok) {
    int dd = tok & 3;
    int nn = (tok >> 2) & 3;
    int tt = (tok >> 4) & 3;
    int n  = (tok >> 6) & 255;
    int Ti = (tok >> 14) & 1;
    int v  = (tok >> 15) & 1;
    return v * 2097152 + (Ti * 4 + tt) * 262144 + (n * 4 + nn) * 256 + dd * 64;
}
__device__ __forceinline__ int tok_of_qrow(int row, int Ti, int n) {
    int dd = row & 3, nn = (row >> 2) & 3, tt = (row >> 4) & 3, v2 = row >> 6;
    return ((((v2 * 2 + Ti) * 256 + n) * 4 + tt) * 4 + nn) * 4 + dd;
}

__device__ __forceinline__ unsigned pack_bf2(float lo, float hi) {
    unsigned ulo = (unsigned)__bfloat16_as_ushort(__float2bfloat16(lo));
    unsigned uhi = (unsigned)__bfloat16_as_ushort(__float2bfloat16(hi));
    return (uhi << 16) | ulo;
}
__device__ __forceinline__ float bf_lo(unsigned u) {
    return __bfloat162float(__ushort_as_bfloat16((unsigned short)(u & 0xffff)));
}
__device__ __forceinline__ float bf_hi(unsigned u) {
    return __bfloat162float(__ushort_as_bfloat16((unsigned short)(u >> 16)));
}

__device__ __forceinline__ void mma16816(float c[4], const unsigned a[4], unsigned b0, unsigned b1) {
    asm volatile(
        "mma.sync.aligned.m16n8k16.row.col.f32.bf16.bf16.f32 "
        "{%0,%1,%2,%3}, {%4,%5,%6,%7}, {%8,%9}, {%0,%1,%2,%3};"
        : "+f"(c[0]), "+f"(c[1]), "+f"(c[2]), "+f"(c[3])
        : "r"(a[0]), "r"(a[1]), "r"(a[2]), "r"(a[3]), "r"(b0), "r"(b1));
}
__device__ __forceinline__ void ldsm4(unsigned r[4], const void* p) {
    unsigned addr = (unsigned)__cvta_generic_to_shared(p);
    asm volatile("ldmatrix.sync.aligned.m8n8.x4.shared.b16 {%0,%1,%2,%3}, [%4];"
        : "=r"(r[0]), "=r"(r[1]), "=r"(r[2]), "=r"(r[3]) : "r"(addr));
}
__device__ __forceinline__ void ldsm4t(unsigned r[4], const void* p) {
    unsigned addr = (unsigned)__cvta_generic_to_shared(p);
    asm volatile("ldmatrix.sync.aligned.m8n8.x4.trans.shared.b16 {%0,%1,%2,%3}, [%4];"
        : "=r"(r[0]), "=r"(r[1]), "=r"(r[2]), "=r"(r[3]) : "r"(addr));
}

// ---------------------------------------------------------------------------
// k_cvt: pack all weights into per-lane fragment order:
//   word[((nt*8+g)*4+t)*2KC + 2*kc + h] = pack(W[k][n], W[k+1][n]),
//   n = nt*8+g, k = 16kc + 2t + 8h
// ---------------------------------------------------------------------------
__global__ void k_cvt(const float* __restrict__ Wq, const float* __restrict__ Wkv,
                      const float* __restrict__ Wo, const float* __restrict__ W1,
                      const float* __restrict__ W2)
{
    int i = blockIdx.x * 256 + threadIdx.x;
    if (i < 12288) {                       // Wqkv: KC=4
        int h = i & 1, kc = (i >> 1) & 3, t = (i >> 3) & 3, g = (i >> 5) & 7, nt = i >> 8;
        int n = nt * 8 + g, k = kc * 16 + 2 * t + 8 * h;
        float v0, v1;
        if (n < 128) { v0 = Wq[k * 128 + n]; v1 = Wq[(k + 1) * 128 + n]; }
        else         { v0 = Wkv[k * 256 + n - 128]; v1 = Wkv[(k + 1) * 256 + n - 128]; }
        WqkvP[i] = pack_bf2(v0, v1);
    } else if (i < 16384) {                // Wo: KC=8
        int j = i - 12288;
        int h = j & 1, kc = (j >> 1) & 7, t = (j >> 4) & 3, g = (j >> 6) & 7, nt = j >> 9;
        int n = nt * 8 + g, k = kc * 16 + 2 * t + 8 * h;
        WoP[j] = pack_bf2(Wo[k * 64 + n], Wo[(k + 1) * 64 + n]);
    } else if (i < 20480) {                // W1: KC=4
        int j = i - 16384;
        int h = j & 1, kc = (j >> 1) & 3, t = (j >> 3) & 3, g = (j >> 5) & 7, nt = j >> 8;
        int n = nt * 8 + g, k = kc * 16 + 2 * t + 8 * h;
        W1P[j] = pack_bf2(W1[k * 128 + n], W1[(k + 1) * 128 + n]);
    } else if (i < 24576) {                // W2: KC=8
        int j = i - 20480;
        int h = j & 1, kc = (j >> 1) & 7, t = (j >> 4) & 3, g = (j >> 6) & 7, nt = j >> 9;
        int n = nt * 8 + g, k = kc * 16 + 2 * t + 8 * h;
        W2P[j] = pack_bf2(W2[k * 64 + n], W2[(k + 1) * 64 + n]);
    }
}

// ---------------------------------------------------------------------------
// k1: LN1 + QKV projection. 64 tokens/CTA, 256 threads (2 Mwarps x 4 Nwarps).
// A-frags via ldmatrix; B via packed LDG.128. q written with SCALE folded in.
// ---------------------------------------------------------------------------
__global__ void __launch_bounds__(256) k1_ln_qkv(
    const float* __restrict__ x,
    const float* __restrict__ ln1_s, const float* __restrict__ ln1_b,
    const float* __restrict__ bkv)
{
    __shared__ unsigned sA[64 * 36];    // 64 rows x 72 bf16 (stride 36 words, 16B aligned, conflict-free)
    const int tid = threadIdx.x;
    const int tokBase = blockIdx.x * 64;

    // --- LN1: 4 lanes per row ---
    {
        int row = tid >> 2, s = tid & 3;
        const float* xr = x + xoff_of_token(tokBase + row);
        float h[16];
        #pragma unroll
        for (int j = 0; j < 4; j++) {
            float4 xv = *(const float4*)(xr + s * 16 + j * 4);
            h[4 * j + 0] = xv.x; h[4 * j + 1] = xv.y; h[4 * j + 2] = xv.z; h[4 * j + 3] = xv.w;
        }
        float a = 0.0f, q2 = 0.0f;
        #pragma unroll
        for (int j = 0; j < 16; j++) { a += h[j]; q2 += h[j] * h[j]; }
        a  += __shfl_xor_sync(0xffffffffu, a, 1);  a  += __shfl_xor_sync(0xffffffffu, a, 2);
        q2 += __shfl_xor_sync(0xffffffffu, q2, 1); q2 += __shfl_xor_sync(0xffffffffu, q2, 2);
        float mean = a * (1.0f / 64.0f);
        float rstd = rsqrtf(q2 * (1.0f / 64.0f) - mean * mean + 1e-5f);
        #pragma unroll
        for (int j = 0; j < 8; j++) {
            int k = s * 16 + 2 * j;
            float h0 = (h[2 * j]     - mean) * rstd * ln1_s[k]     + ln1_b[k];
            float h1 = (h[2 * j + 1] - mean) * rstd * ln1_s[k + 1] + ln1_b[k + 1];
            sA[row * 36 + s * 8 + j] = pack_bf2(h0, h1);
        }
    }
    __syncthreads();

    const int wq = tid >> 5, lane = tid & 31;
    const int mw = wq >> 2, nw = wq & 3;
    const int g = lane >> 2, t = lane & 3;

    // A fragments via ldmatrix.x4: 2 m-tiles x 4 kc
    unsigned a[2][4][4];
    {
        int rin = (lane & 7) + 8 * ((lane >> 3) & 1);
        int half = lane >> 4;
        #pragma unroll
        for (int mt = 0; mt < 2; mt++) {
            int rowg = mw * 32 + mt * 16 + rin;
            #pragma unroll
            for (int kc = 0; kc < 4; kc++)
                ldsm4(a[mt][kc], &sA[rowg * 36 + kc * 8 + half * 4]);
        }
    }

    unsigned* qg = (unsigned*)g_q;
    unsigned* kg = (unsigned*)g_k;
    unsigned* vg = (unsigned*)g_v;

    #pragma unroll
    for (int nt = 0; nt < 12; nt++) {
        float acc0[4] = {0, 0, 0, 0}, acc1[4] = {0, 0, 0, 0};
        int base = (((nw * 12 + nt) * 8 + g) * 4 + t) * 8;
        uint4 u0 = *(const uint4*)&WqkvP[base];
        uint4 u1 = *(const uint4*)&WqkvP[base + 4];
        mma16816(acc0, a[0][0], u0.x, u0.y);
        mma16816(acc0, a[0][1], u0.z, u0.w);
        mma16816(acc0, a[0][2], u1.x, u1.y);
        mma16816(acc0, a[0][3], u1.z, u1.w);
        mma16816(acc1, a[1][0], u0.x, u0.y);
        mma16816(acc1, a[1][1], u0.z, u0.w);
        mma16816(acc1, a[1][2], u1.x, u1.y);
        mma16816(acc1, a[1][3], u1.z, u1.w);

        int n0 = nw * 96 + nt * 8 + 2 * t;
        #pragma unroll
        for (int mt = 0; mt < 2; mt++) {
            float* c = (mt == 0) ? acc0 : acc1;
            int r0 = mw * 32 + mt * 16 + g;
            int tok0 = tokBase + r0, tok1 = tokBase + r0 + 8;
            if (n0 < 128) {
                qg[tok0 * 64 + n0 / 2] = pack_bf2(c[0] * SCALE, c[1] * SCALE);
                qg[tok1 * 64 + n0 / 2] = pack_bf2(c[2] * SCALE, c[3] * SCALE);
            } else if (n0 < 256) {
                float bb0 = bkv[n0 - 128], bb1 = bkv[n0 - 127];
                kg[tok0 * 64 + (n0 - 128) / 2] = pack_bf2(c[0] + bb0, c[1] + bb1);
                kg[tok1 * 64 + (n0 - 128) / 2] = pack_bf2(c[2] + bb0, c[3] + bb1);
            } else {
                float bb0 = bkv[n0 - 128], bb1 = bkv[n0 - 127];
                vg[tok0 * 64 + (n0 - 256) / 2] = pack_bf2(c[0] + bb0, c[1] + bb1);
                vg[tok1 * 64 + (n0 - 256) / 2] = pack_bf2(c[2] + bb0, c[3] + bb1);
            }
        }
    }
}

// ---------------------------------------------------------------------------
// k2: flash attention. CTA = (window, head), 2048 CTAs, 128 threads.
// Whole 192-row KV window resident in smem (1 barrier total).
// K frags via ldmatrix, V^T frags via ldmatrix.trans.
// ---------------------------------------------------------------------------
__global__ void __launch_bounds__(128) k2_attn(const float* __restrict__ bkv)
{
    __shared__ unsigned sK[192 * 20];   // 192 rows x 32 bf16, stride 20 words (80B)
    __shared__ unsigned sV[192 * 20];
    __shared__ float kh[32], vh[32];

    const int bid = blockIdx.x;
    const int hh = bid & 3;
    const int w  = bid >> 2;
    const int Ti = w >> 8;
    const int n  = w & 255;
    const int tid = threadIdx.x;
    const int wid = tid >> 5, lane = tid & 31;
    const int g = lane >> 2, t = lane & 3;
    const int lo = (Ti > 0) ? 2 : 0;

    if (tid < 32) {
        kh[tid] = bkv[hh * 32 + tid];
        vh[tid] = bkv[128 + hh * 32 + tid];
    }

    // cooperative whole-window load: 192 rows x 4 x 16B per array
    {
        const uint4* kg4 = (const uint4*)g_k;
        const uint4* vg4 = (const uint4*)g_v;
        #pragma unroll
        for (int i = 0; i < 6; i++) {
            int c = tid + 128 * i;
            int row = c >> 2, part = c & 3;
            int rdd = row & 3, rnn = (row >> 2) & 3, rt = row >> 4;
            int tsel = rt % 6, v2 = rt / 6;
            int Tsrc, rtt;
            if (tsel < lo)            { Tsrc = Ti - 1; rtt = 2 + tsel; }
            else if (tsel < lo + 4)   { Tsrc = Ti;     rtt = tsel - lo; }
            else                      { Tsrc = Ti + 1; rtt = tsel - lo - 4; }
            int tokR = ((((v2 * 2 + Tsrc) * 256 + n) * 4 + rtt) * 4 + rnn) * 4 + rdd;
            int src = tokR * 16 + hh * 4 + part;   // uint4 index: (tok*64 + hh*16 + part*4)/4
            *(uint4*)&sK[row * 20 + part * 4] = kg4[src];
            *(uint4*)&sV[row * 20 + part * 4] = vg4[src];
        }
    }

    // q fragments (scale folded in)
    const unsigned* qg = (const unsigned*)g_q;
    unsigned qa[2][2][4];
    int tokR0[2], tokR1[2];
    #pragma unroll
    for (int mt = 0; mt < 2; mt++) {
        int r0 = wid * 32 + mt * 16 + g;
        tokR0[mt] = tok_of_qrow(r0, Ti, n);
        tokR1[mt] = tok_of_qrow(r0 + 8, Ti, n);
        int b0 = tokR0[mt] * 64 + hh * 16;
        int b1 = tokR1[mt] * 64 + hh * 16;
        #pragma unroll
        for (int kc = 0; kc < 2; kc++) {
            qa[mt][kc][0] = qg[b0 + kc * 8 + t];
            qa[mt][kc][1] = qg[b1 + kc * 8 + t];
            qa[mt][kc][2] = qg[b0 + kc * 8 + t + 4];
            qa[mt][kc][3] = qg[b1 + kc * 8 + t + 4];
        }
    }

    float m0[2] = {-1e30f, -1e30f}, m1[2] = {-1e30f, -1e30f};
    float l0[2] = {0.0f, 0.0f},    l1[2] = {0.0f, 0.0f};
    float acc[2][4][4];
    #pragma unroll
    for (int mt = 0; mt < 2; mt++)
        #pragma unroll
        for (int ot = 0; ot < 4; ot++)
            #pragma unroll
            for (int e = 0; e < 4; e++) acc[mt][ot][e] = 0.0f;

    __syncthreads();   // the only barrier

    // ldmatrix lane address components
    const int krow_in = lane & 7;            // K: row within tile
    const int kcolw   = (lane >> 3) * 4;     // K: m0..m3 -> col words 0,4,8,12
    const int vrow_in = ((lane >> 3) & 1) * 8 + (lane & 7);
    const int vcolw   = (lane >> 4) * 4;     // V: +4 words for second n8 tile

    for (int c = 0; c < 12; c++) {
        const int n0 = c * 16;

        unsigned kb[2][4];   // [nt]: {kc0.b0, kc0.b1, kc1.b0, kc1.b1}
        #pragma unroll
        for (int nt = 0; nt < 2; nt++)
            ldsm4(kb[nt], &sK[(n0 + nt * 8 + krow_in) * 20 + kcolw]);

        unsigned vb[2][4];   // [op]: {ot(2op).b0, ot(2op).b1, ot(2op+1).b0, ot(2op+1).b1}
        #pragma unroll
        for (int op = 0; op < 2; op++)
            ldsm4t(vb[op], &sV[(n0 + vrow_in) * 20 + op * 8 + vcolw]);

        #pragma unroll
        for (int mt = 0; mt < 2; mt++) {
            float s0[4] = {0, 0, 0, 0}, s1[4] = {0, 0, 0, 0};
            mma16816(s0, qa[mt][0], kb[0][0], kb[0][1]);
            mma16816(s0, qa[mt][1], kb[0][2], kb[0][3]);
            mma16816(s1, qa[mt][0], kb[1][0], kb[1][1]);
            mma16816(s1, qa[mt][1], kb[1][2], kb[1][3]);

            float rmax0 = fmaxf(fmaxf(s0[0], s0[1]), fmaxf(s1[0], s1[1]));
            float rmax1 = fmaxf(fmaxf(s0[2], s0[3]), fmaxf(s1[2], s1[3]));
            rmax0 = fmaxf(rmax0, __shfl_xor_sync(0xffffffffu, rmax0, 1));
            rmax0 = fmaxf(rmax0, __shfl_xor_sync(0xffffffffu, rmax0, 2));
            rmax1 = fmaxf(rmax1, __shfl_xor_sync(0xffffffffu, rmax1, 1));
            rmax1 = fmaxf(rmax1, __shfl_xor_sync(0xffffffffu, rmax1, 2));
            float mn0 = fmaxf(m0[mt], rmax0), mn1 = fmaxf(m1[mt], rmax1);
            float cr0 = __expf(m0[mt] - mn0), cr1 = __expf(m1[mt] - mn1);
            float p00 = __expf(s0[0] - mn0), p01 = __expf(s0[1] - mn0);
            float p10 = __expf(s1[0] - mn0), p11 = __expf(s1[1] - mn0);
            float q00 = __expf(s0[2] - mn1), q01 = __expf(s0[3] - mn1);
            float q10 = __expf(s1[2] - mn1), q11 = __expf(s1[3] - mn1);
            float ps0 = p00 + p01 + p10 + p11;
            float ps1 = q00 + q01 + q10 + q11;
            ps0 += __shfl_xor_sync(0xffffffffu, ps0, 1);
            ps0 += __shfl_xor_sync(0xffffffffu, ps0, 2);
            ps1 += __shfl_xor_sync(0xffffffffu, ps1, 1);
            ps1 += __shfl_xor_sync(0xffffffffu, ps1, 2);
            l0[mt] = l0[mt] * cr0 + ps0;
            l1[mt] = l1[mt] * cr1 + ps1;
            m0[mt] = mn0; m1[mt] = mn1;

            unsigned pa[4];
            pa[0] = pack_bf2(p00, p01);
            pa[1] = pack_bf2(q00, q01);
            pa[2] = pack_bf2(p10, p11);
            pa[3] = pack_bf2(q10, q11);

            #pragma unroll
            for (int ot = 0; ot < 4; ot++) {
                acc[mt][ot][0] *= cr0; acc[mt][ot][1] *= cr0;
                acc[mt][ot][2] *= cr1; acc[mt][ot][3] *= cr1;
                mma16816(acc[mt][ot], pa, vb[ot >> 1][(ot & 1) * 2], vb[ot >> 1][(ot & 1) * 2 + 1]);
            }
        }
    }

    // constant halo column, multiplicity 320
    #pragma unroll
    for (int mt = 0; mt < 2; mt++) {
        float hd0 = 0.0f, hd1 = 0.0f;
        #pragma unroll
        for (int kc = 0; kc < 2; kc++) {
            int kb0 = kc * 16 + 2 * t;
            hd0 += bf_lo(qa[mt][kc][0]) * kh[kb0]     + bf_hi(qa[mt][kc][0]) * kh[kb0 + 1];
            hd0 += bf_lo(qa[mt][kc][2]) * kh[kb0 + 8] + bf_hi(qa[mt][kc][2]) * kh[kb0 + 9];
            hd1 += bf_lo(qa[mt][kc][1]) * kh[kb0]     + bf_hi(qa[mt][kc][1]) * kh[kb0 + 1];
            hd1 += bf_lo(qa[mt][kc][3]) * kh[kb0 + 8] + bf_hi(qa[mt][kc][3]) * kh[kb0 + 9];
        }
        hd0 += __shfl_xor_sync(0xffffffffu, hd0, 1);
        hd0 += __shfl_xor_sync(0xffffffffu, hd0, 2);
        hd1 += __shfl_xor_sync(0xffffffffu, hd1, 1);
        hd1 += __shfl_xor_sync(0xffffffffu, hd1, 2);
        float mn0 = fmaxf(m0[mt], hd0), mn1 = fmaxf(m1[mt], hd1);
        float cr0 = __expf(m0[mt] - mn0), cr1 = __expf(m1[mt] - mn1);
        float ph0 = __expf(hd0 - mn0) * 320.0f;
        float ph1 = __expf(hd1 - mn1) * 320.0f;
        l0[mt] = l0[mt] * cr0 + ph0;
        l1[mt] = l1[mt] * cr1 + ph1;
        #pragma unroll
        for (int ot = 0; ot < 4; ot++) {
            int c0 = ot * 8 + 2 * t;
            acc[mt][ot][0] = acc[mt][ot][0] * cr0 + ph0 * vh[c0];
            acc[mt][ot][1] = acc[mt][ot][1] * cr0 + ph0 * vh[c0 + 1];
            acc[mt][ot][2] = acc[mt][ot][2] * cr1 + ph1 * vh[c0];
            acc[mt][ot][3] = acc[mt][ot][3] * cr1 + ph1 * vh[c0 + 1];
        }
    }

    unsigned* og = (unsigned*)g_o;
    #pragma unroll
    for (int mt = 0; mt < 2; mt++) {
        float inv0 = 1.0f / l0[mt], inv1 = 1.0f / l1[mt];
        int b0 = tokR0[mt] * 64 + hh * 16;
        int b1 = tokR1[mt] * 64 + hh * 16;
        #pragma unroll
        for (int ot = 0; ot < 4; ot++) {
            og[b0 + ot * 4 + t] = pack_bf2(acc[mt][ot][0] * inv0, acc[mt][ot][1] * inv0);
            og[b1 + ot * 4 + t] = pack_bf2(acc[mt][ot][2] * inv1, acc[mt][ot][3] * inv1);
        }
    }
}

// ---------------------------------------------------------------------------
// k3: fused Wo+residual+LN2+MLP1+gelu+MLP2+residual, register-resident.
// 128 threads = 4 warps, each warp owns 16 tokens x all 64 features.
// No smem staging of activations, no inter-stage barriers.
// ---------------------------------------------------------------------------
__global__ void __launch_bounds__(128, 3) k3_post(
    const float* __restrict__ x,
    const float* __restrict__ bo, const float* __restrict__ gamma,
    const float* __restrict__ ln2_s, const float* __restrict__ ln2_b,
    const float* __restrict__ b1, const float* __restrict__ b2,
    const float* __restrict__ gamma_mlp, float* __restrict__ out)
{
    __shared__ float sp[512];
    const int tid = threadIdx.x;
    for (int i = tid; i < 512; i += 128) {
        float v;
        if (i < 64)       v = bo[i];
        else if (i < 128) v = gamma[i - 64];
        else if (i < 192) v = ln2_s[i - 128];
        else if (i < 256) v = ln2_b[i - 192];
        else if (i < 384) v = b1[i - 256];
        else if (i < 448) v = b2[i - 384];
        else              v = gamma_mlp[i - 448];
        sp[i] = v;
    }
    __syncthreads();
    const float* s_bo = sp;        const float* s_gm = sp + 64;
    const float* s_ls = sp + 128;  const float* s_lb = sp + 192;
    const float* s_b1 = sp + 256;  const float* s_b2 = sp + 384;
    const float* s_gmlp = sp + 448;

    const int wid = tid >> 5, lane = tid & 31;
    const int g = lane >> 2, t = lane & 3;
    const int R = blockIdx.x * 64 + wid * 16;
    const int tok0 = R + g, tok1 = R + 8 + g;
    const int xo0 = xoff_of_token(tok0), xo1 = xoff_of_token(tok1);

    const unsigned* og = (const unsigned*)g_o;

    // ---- GEMM1: upd = o @ Wo ; tok = x + gamma*(upd+bo) (registers) ----
    unsigned ao[8][4];
    #pragma unroll
    for (int kc = 0; kc < 8; kc++) {
        ao[kc][0] = og[tok0 * 64 + kc * 8 + t];
        ao[kc][1] = og[tok1 * 64 + kc * 8 + t];
        ao[kc][2] = og[tok0 * 64 + kc * 8 + t + 4];
        ao[kc][3] = og[tok1 * 64 + kc * 8 + t + 4];
    }
    float tok[8][4];
    #pragma unroll
    for (int nt = 0; nt < 8; nt++) {
        float acc[4] = {0, 0, 0, 0};
        int base = ((nt * 8 + g) * 4 + t) * 16;
        uint4 u0 = *(const uint4*)&WoP[base];
        uint4 u1 = *(const uint4*)&WoP[base + 4];
        uint4 u2 = *(const uint4*)&WoP[base + 8];
        uint4 u3 = *(const uint4*)&WoP[base + 12];
        mma16816(acc, ao[0], u0.x, u0.y);
        mma16816(acc, ao[1], u0.z, u0.w);
        mma16816(acc, ao[2], u1.x, u1.y);
        mma16816(acc, ao[3], u1.z, u1.w);
        mma16816(acc, ao[4], u2.x, u2.y);
        mma16816(acc, ao[5], u2.z, u2.w);
        mma16816(acc, ao[6], u3.x, u3.y);
        mma16816(acc, ao[7], u3.z, u3.w);
        int n0 = nt * 8 + 2 * t;
        float2 x0 = *(const float2*)(x + xo0 + n0);
        float2 x1 = *(const float2*)(x + xo1 + n0);
        tok[nt][0] = x0.x + s_gm[n0]     * (acc[0] + s_bo[n0]);
        tok[nt][1] = x0.y + s_gm[n0 + 1] * (acc[1] + s_bo[n0 + 1]);
        tok[nt][2] = x1.x + s_gm[n0]     * (acc[2] + s_bo[n0]);
        tok[nt][3] = x1.y + s_gm[n0 + 1] * (acc[3] + s_bo[n0 + 1]);
    }

    // ---- LN2 in registers (quad shuffle) ----
    float sum0 = 0.0f, sq0 = 0.0f, sum1 = 0.0f, sq1 = 0.0f;
    #pragma unroll
    for (int nt = 0; nt < 8; nt++) {
        sum0 += tok[nt][0] + tok[nt][1];
        sq0  += tok[nt][0] * tok[nt][0] + tok[nt][1] * tok[nt][1];
        sum1 += tok[nt][2] + tok[nt][3];
        sq1  += tok[nt][2] * tok[nt][2] + tok[nt][3] * tok[nt][3];
    }
    sum0 += __shfl_xor_sync(0xffffffffu, sum0, 1); sum0 += __shfl_xor_sync(0xffffffffu, sum0, 2);
    sq0  += __shfl_xor_sync(0xffffffffu, sq0, 1);  sq0  += __shfl_xor_sync(0xffffffffu, sq0, 2);
    sum1 += __shfl_xor_sync(0xffffffffu, sum1, 1); sum1 += __shfl_xor_sync(0xffffffffu, sum1, 2);
    sq1  += __shfl_xor_sync(0xffffffffu, sq1, 1);  sq1  += __shfl_xor_sync(0xffffffffu, sq1, 2);
    float mean0 = sum0 * (1.0f / 64.0f);
    float mean1 = sum1 * (1.0f / 64.0f);
    float rstd0 = rsqrtf(sq0 * (1.0f / 64.0f) - mean0 * mean0 + 1e-5f);
    float rstd1 = rsqrtf(sq1 * (1.0f / 64.0f) - mean1 * mean1 + 1e-5f);

    // h2 packed straight into A-fragment layout (C-tile-pair identity)
    unsigned ah[4][4];
    #pragma unroll
    for (int kc = 0; kc < 4; kc++) {
        int ta = 2 * kc, tb = 2 * kc + 1;
        int ca = ta * 8 + 2 * t, cb = tb * 8 + 2 * t;
        float a0 = (tok[ta][0] - mean0) * rstd0 * s_ls[ca]     + s_lb[ca];
        float a1 = (tok[ta][1] - mean0) * rstd0 * s_ls[ca + 1] + s_lb[ca + 1];
        float a2 = (tok[ta][2] - mean1) * rstd1 * s_ls[ca]     + s_lb[ca];
        float a3 = (tok[ta][3] - mean1) * rstd1 * s_ls[ca + 1] + s_lb[ca + 1];
        float b0f = (tok[tb][0] - mean0) * rstd0 * s_ls[cb]     + s_lb[cb];
        float b1f = (tok[tb][1] - mean0) * rstd0 * s_ls[cb + 1] + s_lb[cb + 1];
        float b2f = (tok[tb][2] - mean1) * rstd1 * s_ls[cb]     + s_lb[cb];
        float b3f = (tok[tb][3] - mean1) * rstd1 * s_ls[cb + 1] + s_lb[cb + 1];
        ah[kc][0] = pack_bf2(a0, a1);
        ah[kc][1] = pack_bf2(a2, a3);
        ah[kc][2] = pack_bf2(b0f, b1f);
        ah[kc][3] = pack_bf2(b2f, b3f);
    }

    // ---- GEMM2: u = h2 @ W1 + b1 ; gelu -> acc2 (fp32 regs) ----
    float acc2[16][4];
    #pragma unroll
    for (int nt = 0; nt < 16; nt++) {
        float acc[4] = {0, 0, 0, 0};
        int base = ((nt * 8 + g) * 4 + t) * 8;
        uint4 u0 = *(const uint4*)&W1P[base];
        uint4 u1 = *(const uint4*)&W1P[base + 4];
        mma16816(acc, ah[0], u0.x, u0.y);
        mma16816(acc, ah[1], u0.z, u0.w);
        mma16816(acc, ah[2], u1.x, u1.y);
        mma16816(acc, ah[3], u1.z, u1.w);
        int n0 = nt * 8 + 2 * t;
        #pragma unroll
        for (int e = 0; e < 4; e++) {
            float uu = acc[e] + s_b1[n0 + (e & 1)];
            float inner = 0.7978845608028654f * (uu + 0.044715f * uu * uu * uu);
            acc2[nt][e] = 0.5f * uu * (1.0f + tanhf(inner));
        }
    }

    // pack gelu output into A fragments for GEMM3
    unsigned aa[8][4];
    #pragma unroll
    for (int kc = 0; kc < 8; kc++) {
        aa[kc][0] = pack_bf2(acc2[2 * kc][0],     acc2[2 * kc][1]);
        aa[kc][1] = pack_bf2(acc2[2 * kc][2],     acc2[2 * kc][3]);
        aa[kc][2] = pack_bf2(acc2[2 * kc + 1][0], acc2[2 * kc + 1][1]);
        aa[kc][3] = pack_bf2(acc2[2 * kc + 1][2], acc2[2 * kc + 1][3]);
    }

    // ---- GEMM3: mlp = a @ W2 + b2 ; out = tok + gamma_mlp*mlp ----
    #pragma unroll
    for (int nt = 0; nt < 8; nt++) {
        float acc[4] = {0, 0, 0, 0};
        int base = ((nt * 8 + g) * 4 + t) * 16;
        uint4 u0 = *(const uint4*)&W2P[base];
        uint4 u1 = *(const uint4*)&W2P[base + 4];
        uint4 u2 = *(const uint4*)&W2P[base + 8];
        uint4 u3 = *(const uint4*)&W2P[base + 12];
        mma16816(acc, aa[0], u0.x, u0.y);
        mma16816(acc, aa[1], u0.z, u0.w);
        mma16816(acc, aa[2], u1.x, u1.y);
        mma16816(acc, aa[3], u1.z, u1.w);
        mma16816(acc, aa[4], u2.x, u2.y);
        mma16816(acc, aa[5], u2.z, u2.w);
        mma16816(acc, aa[6], u3.x, u3.y);
        mma16816(acc, aa[7], u3.z, u3.w);
        int n0 = nt * 8 + 2 * t;
        float2 o0, o1;
        o0.x = tok[nt][0] + s_gmlp[n0]     * (acc[0] + s_b2[n0]);
        o0.y = tok[nt][1] + s_gmlp[n0 + 1] * (acc[1] + s_b2[n0 + 1]);
        o1.x = tok[nt][2] + s_gmlp[n0]     * (acc[2] + s_b2[n0]);
        o1.y = tok[nt][3] + s_gmlp[n0 + 1] * (acc[3] + s_b2[n0 + 1]);
        *(float2*)(out + xo0 + n0) = o0;
        *(float2*)(out + xo1 + n0) = o1;
    }
}

// ---------------------------------------------------------------------------
extern "C" void kernel_launch(void* const* d_in, const int* in_sizes, int n_in,
                              void* d_out, int out_size)
{
    (void)in_sizes; (void)n_in; (void)out_size;
    const float* x         = (const float*)d_in[0];
    const float* ln1_s     = (const float*)d_in[1];
    const float* ln1_b     = (const float*)d_in[2];
    const float* Wq        = (const float*)d_in[3];
    const float* Wkv       = (const float*)d_in[4];
    const float* bkv       = (const float*)d_in[5];
    const float* Wo        = (const float*)d_in[6];
    const float* bo        = (const float*)d_in[7];
    const float* gamma     = (const float*)d_in[8];
    const float* ln2_s     = (const float*)d_in[9];
    const float* ln2_b     = (const float*)d_in[10];
    const float* W1        = (const float*)d_in[11];
    const float* b1        = (const float*)d_in[12];
    const float* W2        = (const float*)d_in[13];
    const float* b2        = (const float*)d_in[14];
    const float* gamma_mlp = (const float*)d_in[15];
    float* out = (float*)d_out;

    k_cvt<<<96, 256>>>(Wq, Wkv, Wo, W1, W2);
    k1_ln_qkv<<<NTOK / 64, 256>>>(x, ln1_s, ln1_b, bkv);
    k2_attn<<<512 * 4, 128>>>(bkv);
    k3_post<<<NTOK / 64, 128>>>(x, bo, gamma, ln2_s, ln2_b, b1, b2, gamma_mlp, out);
}

// round 4
// speedup vs baseline: 7.2761x; 1.1393x over previous
#include <cuda_runtime.h>
#include <cuda_bf16.h>
#include <math.h>

#define NTOK 65536
#define SCALE 0.17677669529663687f   // 1/sqrt(32), folded into q

// ---------------- device scratch ----------------
// q and o in consumer mma A-fragment order:
//   word[((blk*8 + kc)*32 + lane)*4 + e], blk = token/16, kc = word/8,
//   e: 0=tok(g) low-half, 1=tok(g+8) low, 2=tok(g) high, 3=tok(g+8) high
__device__ unsigned g_qF[NTOK * 64];
__device__ unsigned g_oF[NTOK * 64];
// k/v head-major: word[hh*NTOK*16 + tok*16 + w16]
__device__ unsigned g_kH[4 * NTOK * 16];
__device__ unsigned g_vH[4 * NTOK * 16];
// weights packed in per-lane mma B-fragment order
__device__ unsigned WqkvP[12288];   // N=384, K=64  (KC=4, NT=48)
__device__ unsigned WoP[4096];      // N=64,  K=128 (KC=8, NT=8)
__device__ unsigned W1P[4096];      // N=128, K=64  (KC=4, NT=16)
__device__ unsigned W2P[4096];      // N=64,  K=128 (KC=8, NT=8)

// token index: ((((v*2 + Ti)*256 + n)*4 + tt)*4 + nn)*4 + dd
__device__ __forceinline__ int xoff_of_token(int tok) {
    int dd = tok & 3;
    int nn = (tok >> 2) & 3;
    int tt = (tok >> 4) & 3;
    int n  = (tok >> 6) & 255;
    int Ti = (tok >> 14) & 1;
    int v  = (tok >> 15) & 1;
    return v * 2097152 + (Ti * 4 + tt) * 262144 + (n * 4 + nn) * 256 + dd * 64;
}

__device__ __forceinline__ unsigned pack_bf2(float lo, float hi) {
    unsigned ulo = (unsigned)__bfloat16_as_ushort(__float2bfloat16(lo));
    unsigned uhi = (unsigned)__bfloat16_as_ushort(__float2bfloat16(hi));
    return (uhi << 16) | ulo;
}
__device__ __forceinline__ float bf_lo(unsigned u) {
    return __bfloat162float(__ushort_as_bfloat16((unsigned short)(u & 0xffff)));
}
__device__ __forceinline__ float bf_hi(unsigned u) {
    return __bfloat162float(__ushort_as_bfloat16((unsigned short)(u >> 16)));
}
__device__ __forceinline__ float tanha(float x) {
    float y; asm("tanh.approx.f32 %0, %1;" : "=f"(y) : "f"(x)); return y;
}

__device__ __forceinline__ void mma16816(float c[4], const unsigned a[4], unsigned b0, unsigned b1) {
    asm volatile(
        "mma.sync.aligned.m16n8k16.row.col.f32.bf16.bf16.f32 "
        "{%0,%1,%2,%3}, {%4,%5,%6,%7}, {%8,%9}, {%0,%1,%2,%3};"
        : "+f"(c[0]), "+f"(c[1]), "+f"(c[2]), "+f"(c[3])
        : "r"(a[0]), "r"(a[1]), "r"(a[2]), "r"(a[3]), "r"(b0), "r"(b1));
}
__device__ __forceinline__ void ldsm4(unsigned r[4], const void* p) {
    unsigned addr = (unsigned)__cvta_generic_to_shared(p);
    asm volatile("ldmatrix.sync.aligned.m8n8.x4.shared.b16 {%0,%1,%2,%3}, [%4];"
        : "=r"(r[0]), "=r"(r[1]), "=r"(r[2]), "=r"(r[3]) : "r"(addr));
}
__device__ __forceinline__ void ldsm4t(unsigned r[4], const void* p) {
    unsigned addr = (unsigned)__cvta_generic_to_shared(p);
    asm volatile("ldmatrix.sync.aligned.m8n8.x4.trans.shared.b16 {%0,%1,%2,%3}, [%4];"
        : "=r"(r[0]), "=r"(r[1]), "=r"(r[2]), "=r"(r[3]) : "r"(addr));
}

// ---------------------------------------------------------------------------
// k_cvt: pack all weights into per-lane fragment order
// ---------------------------------------------------------------------------
__global__ void k_cvt(const float* __restrict__ Wq, const float* __restrict__ Wkv,
                      const float* __restrict__ Wo, const float* __restrict__ W1,
                      const float* __restrict__ W2)
{
    int i = blockIdx.x * 256 + threadIdx.x;
    if (i < 12288) {                       // Wqkv: KC=4
        int h = i & 1, kc = (i >> 1) & 3, t = (i >> 3) & 3, g = (i >> 5) & 7, nt = i >> 8;
        int n = nt * 8 + g, k = kc * 16 + 2 * t + 8 * h;
        float v0, v1;
        if (n < 128) { v0 = Wq[k * 128 + n]; v1 = Wq[(k + 1) * 128 + n]; }
        else         { v0 = Wkv[k * 256 + n - 128]; v1 = Wkv[(k + 1) * 256 + n - 128]; }
        WqkvP[i] = pack_bf2(v0, v1);
    } else if (i < 16384) {                // Wo: KC=8
        int j = i - 12288;
        int h = j & 1, kc = (j >> 1) & 7, t = (j >> 4) & 3, g = (j >> 6) & 7, nt = j >> 9;
        int n = nt * 8 + g, k = kc * 16 + 2 * t + 8 * h;
        WoP[j] = pack_bf2(Wo[k * 64 + n], Wo[(k + 1) * 64 + n]);
    } else if (i < 20480) {                // W1: KC=4
        int j = i - 16384;
        int h = j & 1, kc = (j >> 1) & 3, t = (j >> 3) & 3, g = (j >> 5) & 7, nt = j >> 8;
        int n = nt * 8 + g, k = kc * 16 + 2 * t + 8 * h;
        W1P[j] = pack_bf2(W1[k * 128 + n], W1[(k + 1) * 128 + n]);
    } else if (i < 24576) {                // W2: KC=8
        int j = i - 20480;
        int h = j & 1, kc = (j >> 1) & 7, t = (j >> 4) & 3, g = (j >> 6) & 7, nt = j >> 9;
        int n = nt * 8 + g, k = kc * 16 + 2 * t + 8 * h;
        W2P[j] = pack_bf2(W2[k * 64 + n], W2[(k + 1) * 64 + n]);
    }
}

// ---------------------------------------------------------------------------
// k1: LN1 + QKV projection. 64 tokens/CTA, 256 threads (2 Mwarps x 4 Nwarps).
// q written to g_qF fragment layout (SCALE folded); k/v head-major.
// ---------------------------------------------------------------------------
__global__ void __launch_bounds__(256) k1_ln_qkv(
    const float* __restrict__ x,
    const float* __restrict__ ln1_s, const float* __restrict__ ln1_b,
    const float* __restrict__ bkv)
{
    __shared__ unsigned sA[64 * 36];
    const int tid = threadIdx.x;
    const int tokBase = blockIdx.x * 64;

    // --- LN1: 4 lanes per row ---
    {
        int row = tid >> 2, s = tid & 3;
        const float* xr = x + xoff_of_token(tokBase + row);
        float h[16];
        #pragma unroll
        for (int j = 0; j < 4; j++) {
            float4 xv = *(const float4*)(xr + s * 16 + j * 4);
            h[4 * j + 0] = xv.x; h[4 * j + 1] = xv.y; h[4 * j + 2] = xv.z; h[4 * j + 3] = xv.w;
        }
        float a = 0.0f, q2 = 0.0f;
        #pragma unroll
        for (int j = 0; j < 16; j++) { a += h[j]; q2 += h[j] * h[j]; }
        a  += __shfl_xor_sync(0xffffffffu, a, 1);  a  += __shfl_xor_sync(0xffffffffu, a, 2);
        q2 += __shfl_xor_sync(0xffffffffu, q2, 1); q2 += __shfl_xor_sync(0xffffffffu, q2, 2);
        float mean = a * (1.0f / 64.0f);
        float rstd = rsqrtf(q2 * (1.0f / 64.0f) - mean * mean + 1e-5f);
        #pragma unroll
        for (int j = 0; j < 8; j++) {
            int k = s * 16 + 2 * j;
            float h0 = (h[2 * j]     - mean) * rstd * ln1_s[k]     + ln1_b[k];
            float h1 = (h[2 * j + 1] - mean) * rstd * ln1_s[k + 1] + ln1_b[k + 1];
            sA[row * 36 + s * 8 + j] = pack_bf2(h0, h1);
        }
    }
    __syncthreads();

    const int wq = tid >> 5, lane = tid & 31;
    const int mw = wq >> 2, nw = wq & 3;
    const int g = lane >> 2, t = lane & 3;

    unsigned a[2][4][4];
    {
        int rin = (lane & 7) + 8 * ((lane >> 3) & 1);
        int half = lane >> 4;
        #pragma unroll
        for (int mt = 0; mt < 2; mt++) {
            int rowg = mw * 32 + mt * 16 + rin;
            #pragma unroll
            for (int kc = 0; kc < 4; kc++)
                ldsm4(a[mt][kc], &sA[rowg * 36 + kc * 8 + half * 4]);
        }
    }

    const int blk0 = blockIdx.x * 4 + mw * 2;

    #pragma unroll
    for (int nt = 0; nt < 12; nt++) {
        float acc0[4] = {0, 0, 0, 0}, acc1[4] = {0, 0, 0, 0};
        int base = (((nw * 12 + nt) * 8 + g) * 4 + t) * 8;
        uint4 u0 = *(const uint4*)&WqkvP[base];
        uint4 u1 = *(const uint4*)&WqkvP[base + 4];
        mma16816(acc0, a[0][0], u0.x, u0.y);
        mma16816(acc0, a[0][1], u0.z, u0.w);
        mma16816(acc0, a[0][2], u1.x, u1.y);
        mma16816(acc0, a[0][3], u1.z, u1.w);
        mma16816(acc1, a[1][0], u0.x, u0.y);
        mma16816(acc1, a[1][1], u0.z, u0.w);
        mma16816(acc1, a[1][2], u1.x, u1.y);
        mma16816(acc1, a[1][3], u1.z, u1.w);

        int idx = nw * 48 + nt * 4;      // word base (t excluded)
        int w = idx + t;
        int n0 = 2 * idx + 2 * t;
        #pragma unroll
        for (int mt = 0; mt < 2; mt++) {
            float* c = (mt == 0) ? acc0 : acc1;
            int tok0 = tokBase + mw * 32 + mt * 16 + g;
            int tok1 = tok0 + 8;
            if (idx < 64) {            // q -> fragment layout
                int hh = w >> 4, kc2 = (w >> 3) & 1, half = nt & 1;
                int addr = (((blk0 + mt) * 8 + hh * 2 + kc2) * 32 + lane) * 4 + half * 2;
                *(uint2*)&g_qF[addr] = make_uint2(pack_bf2(c[0] * SCALE, c[1] * SCALE),
                                                  pack_bf2(c[2] * SCALE, c[3] * SCALE));
            } else if (idx < 128) {    // k -> head-major
                int w64 = w - 64, hh = w64 >> 4, w16 = w64 & 15;
                float bb0 = bkv[n0 - 128], bb1 = bkv[n0 - 127];
                g_kH[hh * (NTOK * 16) + tok0 * 16 + w16] = pack_bf2(c[0] + bb0, c[1] + bb1);
                g_kH[hh * (NTOK * 16) + tok1 * 16 + w16] = pack_bf2(c[2] + bb0, c[3] + bb1);
            } else {                   // v -> head-major
                int w64 = w - 128, hh = w64 >> 4, w16 = w64 & 15;
                float bb0 = bkv[n0 - 256], bb1 = bkv[n0 - 255];
                g_vH[hh * (NTOK * 16) + tok0 * 16 + w16] = pack_bf2(c[0] + bb0, c[1] + bb1);
                g_vH[hh * (NTOK * 16) + tok1 * 16 + w16] = pack_bf2(c[2] + bb0, c[3] + bb1);
            }
        }
    }
}

// ---------------------------------------------------------------------------
// k2: flash attention, no running max (scores are tiny; exp safe with max=0).
// CTA = (window, head), 2048 CTAs, 128 threads. Whole 192-row KV in smem.
// ---------------------------------------------------------------------------
__global__ void __launch_bounds__(128) k2_attn(const float* __restrict__ bkv)
{
    __shared__ unsigned sK[192 * 20];
    __shared__ unsigned sV[192 * 20];
    __shared__ float kh[32], vh[32];

    const int bid = blockIdx.x;
    const int hh = bid & 3;
    const int w  = bid >> 2;
    const int Ti = w >> 8;
    const int n  = w & 255;
    const int tid = threadIdx.x;
    const int wid = tid >> 5, lane = tid & 31;
    const int g = lane >> 2, t = lane & 3;
    const int lo = (Ti > 0) ? 2 : 0;

    if (tid < 32) {
        kh[tid] = bkv[hh * 32 + tid];
        vh[tid] = bkv[128 + hh * 32 + tid];
    }

    // cooperative whole-window load (head-major -> contiguous runs)
    {
        const uint4* kg4 = (const uint4*)g_kH;
        const uint4* vg4 = (const uint4*)g_vH;
        #pragma unroll
        for (int i = 0; i < 6; i++) {
            int c = tid + 128 * i;
            int row = c >> 2, part = c & 3;
            int rdd = row & 3, rnn = (row >> 2) & 3, rt = row >> 4;
            int tsel = rt % 6, v2 = rt / 6;
            int Tsrc, rtt;
            if (tsel < lo)            { Tsrc = Ti - 1; rtt = 2 + tsel; }
            else if (tsel < lo + 4)   { Tsrc = Ti;     rtt = tsel - lo; }
            else                      { Tsrc = Ti + 1; rtt = tsel - lo - 4; }
            int tokR = ((((v2 * 2 + Tsrc) * 256 + n) * 4 + rtt) * 4 + rnn) * 4 + rdd;
            int src = hh * (NTOK * 4) + tokR * 4 + part;
            *(uint4*)&sK[row * 20 + part * 4] = kg4[src];
            *(uint4*)&sV[row * 20 + part * 4] = vg4[src];
        }
    }

    // q fragments via coalesced LDG.128
    unsigned qa[2][2][4];
    int blkm[2];
    #pragma unroll
    for (int mt = 0; mt < 2; mt++) {
        int r0 = wid * 32 + mt * 16;
        int tt = (r0 >> 4) & 3, v2 = r0 >> 6;
        blkm[mt] = (((v2 * 2 + Ti) * 256 + n) * 4 + tt);
        #pragma unroll
        for (int kc = 0; kc < 2; kc++) {
            uint4 u = *(const uint4*)&g_qF[((blkm[mt] * 8 + hh * 2 + kc) * 32 + lane) * 4];
            qa[mt][kc][0] = u.x; qa[mt][kc][1] = u.y; qa[mt][kc][2] = u.z; qa[mt][kc][3] = u.w;
        }
    }

    float lp0[2] = {0.0f, 0.0f}, lp1[2] = {0.0f, 0.0f};
    float acc[2][4][4];
    #pragma unroll
    for (int mt = 0; mt < 2; mt++)
        #pragma unroll
        for (int ot = 0; ot < 4; ot++)
            #pragma unroll
            for (int e = 0; e < 4; e++) acc[mt][ot][e] = 0.0f;

    __syncthreads();

    const int krow_in = lane & 7;
    const int kcolw   = (lane >> 3) * 4;
    const int vrow_in = ((lane >> 3) & 1) * 8 + (lane & 7);
    const int vcolw   = (lane >> 4) * 4;

    for (int c = 0; c < 12; c++) {
        const int n0 = c * 16;

        unsigned kb[2][4];
        #pragma unroll
        for (int nt = 0; nt < 2; nt++)
            ldsm4(kb[nt], &sK[(n0 + nt * 8 + krow_in) * 20 + kcolw]);

        unsigned vb[2][4];
        #pragma unroll
        for (int op = 0; op < 2; op++)
            ldsm4t(vb[op], &sV[(n0 + vrow_in) * 20 + op * 8 + vcolw]);

        #pragma unroll
        for (int mt = 0; mt < 2; mt++) {
            float s0[4] = {0, 0, 0, 0}, s1[4] = {0, 0, 0, 0};
            mma16816(s0, qa[mt][0], kb[0][0], kb[0][1]);
            mma16816(s0, qa[mt][1], kb[0][2], kb[0][3]);
            mma16816(s1, qa[mt][0], kb[1][0], kb[1][1]);
            mma16816(s1, qa[mt][1], kb[1][2], kb[1][3]);

            float p00 = __expf(s0[0]), p01 = __expf(s0[1]);
            float p10 = __expf(s1[0]), p11 = __expf(s1[1]);
            float q00 = __expf(s0[2]), q01 = __expf(s0[3]);
            float q10 = __expf(s1[2]), q11 = __expf(s1[3]);
            lp0[mt] += (p00 + p01) + (p10 + p11);
            lp1[mt] += (q00 + q01) + (q10 + q11);

            unsigned pa[4];
            pa[0] = pack_bf2(p00, p01);
            pa[1] = pack_bf2(q00, q01);
            pa[2] = pack_bf2(p10, p11);
            pa[3] = pack_bf2(q10, q11);

            mma16816(acc[mt][0], pa, vb[0][0], vb[0][1]);
            mma16816(acc[mt][1], pa, vb[0][2], vb[0][3]);
            mma16816(acc[mt][2], pa, vb[1][0], vb[1][1]);
            mma16816(acc[mt][3], pa, vb[1][2], vb[1][3]);
        }
    }

    // epilogue: halo column (multiplicity 320) + normalize + write oF
    #pragma unroll
    for (int mt = 0; mt < 2; mt++) {
        float hd0 = 0.0f, hd1 = 0.0f;
        #pragma unroll
        for (int kc = 0; kc < 2; kc++) {
            int kb0 = kc * 16 + 2 * t;
            hd0 += bf_lo(qa[mt][kc][0]) * kh[kb0]     + bf_hi(qa[mt][kc][0]) * kh[kb0 + 1];
            hd0 += bf_lo(qa[mt][kc][2]) * kh[kb0 + 8] + bf_hi(qa[mt][kc][2]) * kh[kb0 + 9];
            hd1 += bf_lo(qa[mt][kc][1]) * kh[kb0]     + bf_hi(qa[mt][kc][1]) * kh[kb0 + 1];
            hd1 += bf_lo(qa[mt][kc][3]) * kh[kb0 + 8] + bf_hi(qa[mt][kc][3]) * kh[kb0 + 9];
        }
        hd0 += __shfl_xor_sync(0xffffffffu, hd0, 1);
        hd0 += __shfl_xor_sync(0xffffffffu, hd0, 2);
        hd1 += __shfl_xor_sync(0xffffffffu, hd1, 1);
        hd1 += __shfl_xor_sync(0xffffffffu, hd1, 2);
        float l0 = lp0[mt], l1 = lp1[mt];
        l0 += __shfl_xor_sync(0xffffffffu, l0, 1);
        l0 += __shfl_xor_sync(0xffffffffu, l0, 2);
        l1 += __shfl_xor_sync(0xffffffffu, l1, 1);
        l1 += __shfl_xor_sync(0xffffffffu, l1, 2);
        float ph0 = __expf(hd0) * 320.0f;
        float ph1 = __expf(hd1) * 320.0f;
        float inv0 = 1.0f / (l0 + ph0);
        float inv1 = 1.0f / (l1 + ph1);

        #pragma unroll
        for (int ot = 0; ot < 4; ot++) {
            int c0 = ot * 8 + 2 * t;
            float f0 = (acc[mt][ot][0] + ph0 * vh[c0])     * inv0;
            float f1 = (acc[mt][ot][1] + ph0 * vh[c0 + 1]) * inv0;
            float f2 = (acc[mt][ot][2] + ph1 * vh[c0])     * inv1;
            float f3 = (acc[mt][ot][3] + ph1 * vh[c0 + 1]) * inv1;
            int addr = ((blkm[mt] * 8 + hh * 2 + (ot >> 1)) * 32 + lane) * 4 + (ot & 1) * 2;
            *(uint2*)&g_oF[addr] = make_uint2(pack_bf2(f0, f1), pack_bf2(f2, f3));
        }
    }
}

// ---------------------------------------------------------------------------
// k3: fused Wo+residual+LN2+MLP1+gelu+MLP2+residual, register-resident.
// x staged in via coalesced coop load; out staged via coalesced coop store.
// ---------------------------------------------------------------------------
__global__ void __launch_bounds__(128, 3) k3_post(
    const float* __restrict__ x,
    const float* __restrict__ bo, const float* __restrict__ gamma,
    const float* __restrict__ ln2_s, const float* __restrict__ ln2_b,
    const float* __restrict__ b1, const float* __restrict__ b2,
    const float* __restrict__ gamma_mlp, float* __restrict__ out)
{
    __shared__ float sp[512];
    __shared__ float4 sxF[4 * 264];   // [wid]: nt*33 + lane, padded
    __shared__ float4 soF[4 * 264];
    const int tid = threadIdx.x;
    for (int i = tid; i < 512; i += 128) {
        float v;
        if (i < 64)       v = bo[i];
        else if (i < 128) v = gamma[i - 64];
        else if (i < 192) v = ln2_s[i - 128];
        else if (i < 256) v = ln2_b[i - 192];
        else if (i < 384) v = b1[i - 256];
        else if (i < 448) v = b2[i - 384];
        else              v = gamma_mlp[i - 448];
        sp[i] = v;
    }
    const float* s_bo = sp;        const float* s_gm = sp + 64;
    const float* s_ls = sp + 128;  const float* s_lb = sp + 192;
    const float* s_b1 = sp + 256;  const float* s_b2 = sp + 384;
    const float* s_gmlp = sp + 448;

    const int R0 = blockIdx.x * 64;
    const int xbase = xoff_of_token(R0);

    // coop coalesced x load -> fragment-order smem
    for (int j = tid; j < 1024; j += 128) {
        int tt = j >> 8, rem = j & 255;
        float4 v = *(const float4*)(x + xbase + tt * 262144 + (rem >> 4) * 64 + (rem & 15) * 4);
        int tk6 = tt * 16 + (rem >> 4);
        int wdst = tk6 >> 4, gg = tk6 & 7, e = (tk6 >> 3) & 1;
        int f0 = (rem & 15) * 4;
        int t0 = (f0 >> 1) & 3, nt = f0 >> 3;
        float2* b2p = (float2*)&sxF[wdst * 264 + nt * 33];
        int li0 = gg * 4 + t0;
        b2p[li0 * 2 + e]       = make_float2(v.x, v.y);
        b2p[(li0 + 1) * 2 + e] = make_float2(v.z, v.w);
    }
    __syncthreads();

    const int wid = tid >> 5, lane = tid & 31;
    const int g = lane >> 2, t = lane & 3;
    const int blk = blockIdx.x * 4 + wid;

    // ---- GEMM1: upd = o @ Wo ; tok = x + gamma*(upd+bo) ----
    unsigned ao[8][4];
    #pragma unroll
    for (int kc = 0; kc < 8; kc++) {
        uint4 u = *(const uint4*)&g_oF[((blk * 8 + kc) * 32 + lane) * 4];
        ao[kc][0] = u.x; ao[kc][1] = u.y; ao[kc][2] = u.z; ao[kc][3] = u.w;
    }
    float tok[8][4];
    #pragma unroll
    for (int nt = 0; nt < 8; nt++) {
        float acc[4] = {0, 0, 0, 0};
        int base = ((nt * 8 + g) * 4 + t) * 16;
        uint4 u0 = *(const uint4*)&WoP[base];
        uint4 u1 = *(const uint4*)&WoP[base + 4];
        uint4 u2 = *(const uint4*)&WoP[base + 8];
        uint4 u3 = *(const uint4*)&WoP[base + 12];
        mma16816(acc, ao[0], u0.x, u0.y);
        mma16816(acc, ao[1], u0.z, u0.w);
        mma16816(acc, ao[2], u1.x, u1.y);
        mma16816(acc, ao[3], u1.z, u1.w);
        mma16816(acc, ao[4], u2.x, u2.y);
        mma16816(acc, ao[5], u2.z, u2.w);
        mma16816(acc, ao[6], u3.x, u3.y);
        mma16816(acc, ao[7], u3.z, u3.w);
        int n0 = nt * 8 + 2 * t;
        float4 xf = sxF[wid * 264 + nt * 33 + lane];
        tok[nt][0] = xf.x + s_gm[n0]     * (acc[0] + s_bo[n0]);
        tok[nt][1] = xf.y + s_gm[n0 + 1] * (acc[1] + s_bo[n0 + 1]);
        tok[nt][2] = xf.z + s_gm[n0]     * (acc[2] + s_bo[n0]);
        tok[nt][3] = xf.w + s_gm[n0 + 1] * (acc[3] + s_bo[n0 + 1]);
    }

    // ---- LN2 in registers ----
    float sum0 = 0.0f, sq0 = 0.0f, sum1 = 0.0f, sq1 = 0.0f;
    #pragma unroll
    for (int nt = 0; nt < 8; nt++) {
        sum0 += tok[nt][0] + tok[nt][1];
        sq0  += tok[nt][0] * tok[nt][0] + tok[nt][1] * tok[nt][1];
        sum1 += tok[nt][2] + tok[nt][3];
        sq1  += tok[nt][2] * tok[nt][2] + tok[nt][3] * tok[nt][3];
    }
    sum0 += __shfl_xor_sync(0xffffffffu, sum0, 1); sum0 += __shfl_xor_sync(0xffffffffu, sum0, 2);
    sq0  += __shfl_xor_sync(0xffffffffu, sq0, 1);  sq0  += __shfl_xor_sync(0xffffffffu, sq0, 2);
    sum1 += __shfl_xor_sync(0xffffffffu, sum1, 1); sum1 += __shfl_xor_sync(0xffffffffu, sum1, 2);
    sq1  += __shfl_xor_sync(0xffffffffu, sq1, 1);  sq1  += __shfl_xor_sync(0xffffffffu, sq1, 2);
    float mean0 = sum0 * (1.0f / 64.0f);
    float mean1 = sum1 * (1.0f / 64.0f);
    float rstd0 = rsqrtf(sq0 * (1.0f / 64.0f) - mean0 * mean0 + 1e-5f);
    float rstd1 = rsqrtf(sq1 * (1.0f / 64.0f) - mean1 * mean1 + 1e-5f);

    unsigned ah[4][4];
    #pragma unroll
    for (int kc = 0; kc < 4; kc++) {
        int ta = 2 * kc, tb = 2 * kc + 1;
        int ca = ta * 8 + 2 * t, cb = tb * 8 + 2 * t;
        float a0 = (tok[ta][0] - mean0) * rstd0 * s_ls[ca]     + s_lb[ca];
        float a1 = (tok[ta][1] - mean0) * rstd0 * s_ls[ca + 1] + s_lb[ca + 1];
        float a2 = (tok[ta][2] - mean1) * rstd1 * s_ls[ca]     + s_lb[ca];
        float a3 = (tok[ta][3] - mean1) * rstd1 * s_ls[ca + 1] + s_lb[ca + 1];
        float bb0 = (tok[tb][0] - mean0) * rstd0 * s_ls[cb]     + s_lb[cb];
        float bb1 = (tok[tb][1] - mean0) * rstd0 * s_ls[cb + 1] + s_lb[cb + 1];
        float bb2 = (tok[tb][2] - mean1) * rstd1 * s_ls[cb]     + s_lb[cb];
        float bb3 = (tok[tb][3] - mean1) * rstd1 * s_ls[cb + 1] + s_lb[cb + 1];
        ah[kc][0] = pack_bf2(a0, a1);
        ah[kc][1] = pack_bf2(a2, a3);
        ah[kc][2] = pack_bf2(bb0, bb1);
        ah[kc][3] = pack_bf2(bb2, bb3);
    }

    // ---- GEMM2 + gelu + A-frag pack, fused per kc pair ----
    unsigned aa[8][4];
    #pragma unroll
    for (int kc2 = 0; kc2 < 8; kc2++) {
        float accA[4] = {0, 0, 0, 0}, accB[4] = {0, 0, 0, 0};
        int ntA = 2 * kc2, ntB = ntA + 1;
        int baseA = ((ntA * 8 + g) * 4 + t) * 8;
        int baseB = ((ntB * 8 + g) * 4 + t) * 8;
        uint4 a0 = *(const uint4*)&W1P[baseA];
        uint4 a1 = *(const uint4*)&W1P[baseA + 4];
        uint4 b0 = *(const uint4*)&W1P[baseB];
        uint4 b1 = *(const uint4*)&W1P[baseB + 4];
        mma16816(accA, ah[0], a0.x, a0.y);
        mma16816(accA, ah[1], a0.z, a0.w);
        mma16816(accA, ah[2], a1.x, a1.y);
        mma16816(accA, ah[3], a1.z, a1.w);
        mma16816(accB, ah[0], b0.x, b0.y);
        mma16816(accB, ah[1], b0.z, b0.w);
        mma16816(accB, ah[2], b1.x, b1.y);
        mma16816(accB, ah[3], b1.z, b1.w);
        int nA = ntA * 8 + 2 * t, nB = ntB * 8 + 2 * t;
        float gA[4], gB[4];
        #pragma unroll
        for (int e = 0; e < 4; e++) {
            float uu = accA[e] + s_b1[nA + (e & 1)];
            float inner = 0.7978845608028654f * (uu + 0.044715f * uu * uu * uu);
            gA[e] = 0.5f * uu * (1.0f + tanha(inner));
            float vv = accB[e] + s_b1[nB + (e & 1)];
            float inner2 = 0.7978845608028654f * (vv + 0.044715f * vv * vv * vv);
            gB[e] = 0.5f * vv * (1.0f + tanha(inner2));
        }
        aa[kc2][0] = pack_bf2(gA[0], gA[1]);
        aa[kc2][1] = pack_bf2(gA[2], gA[3]);
        aa[kc2][2] = pack_bf2(gB[0], gB[1]);
        aa[kc2][3] = pack_bf2(gB[2], gB[3]);
    }

    // ---- GEMM3 -> soF ----
    #pragma unroll
    for (int nt = 0; nt < 8; nt++) {
        float acc[4] = {0, 0, 0, 0};
        int base = ((nt * 8 + g) * 4 + t) * 16;
        uint4 u0 = *(const uint4*)&W2P[base];
        uint4 u1 = *(const uint4*)&W2P[base + 4];
        uint4 u2 = *(const uint4*)&W2P[base + 8];
        uint4 u3 = *(const uint4*)&W2P[base + 12];
        mma16816(acc, aa[0], u0.x, u0.y);
        mma16816(acc, aa[1], u0.z, u0.w);
        mma16816(acc, aa[2], u1.x, u1.y);
        mma16816(acc, aa[3], u1.z, u1.w);
        mma16816(acc, aa[4], u2.x, u2.y);
        mma16816(acc, aa[5], u2.z, u2.w);
        mma16816(acc, aa[6], u3.x, u3.y);
        mma16816(acc, aa[7], u3.z, u3.w);
        int n0 = nt * 8 + 2 * t;
        float4 o;
        o.x = tok[nt][0] + s_gmlp[n0]     * (acc[0] + s_b2[n0]);
        o.y = tok[nt][1] + s_gmlp[n0 + 1] * (acc[1] + s_b2[n0 + 1]);
        o.z = tok[nt][2] + s_gmlp[n0]     * (acc[2] + s_b2[n0]);
        o.w = tok[nt][3] + s_gmlp[n0 + 1] * (acc[3] + s_b2[n0 + 1]);
        soF[wid * 264 + nt * 33 + lane] = o;
    }
    __syncthreads();

    // coop coalesced store
    for (int j = tid; j < 1024; j += 128) {
        int tt = j >> 8, rem = j & 255;
        int tk6 = tt * 16 + (rem >> 4);
        int wsrc = tk6 >> 4, gg = tk6 & 7, e = (tk6 >> 3) & 1;
        int f0 = (rem & 15) * 4;
        int t0 = (f0 >> 1) & 3, nt = f0 >> 3;
        const float2* b2p = (const float2*)&soF[wsrc * 264 + nt * 33];
        int li0 = gg * 4 + t0;
        float2 va = b2p[li0 * 2 + e];
        float2 vb = b2p[(li0 + 1) * 2 + e];
        *(float4*)(out + xbase + tt * 262144 + (rem >> 4) * 64 + f0) =
            make_float4(va.x, va.y, vb.x, vb.y);
    }
}

// ---------------------------------------------------------------------------
extern "C" void kernel_launch(void* const* d_in, const int* in_sizes, int n_in,
                              void* d_out, int out_size)
{
    (void)in_sizes; (void)n_in; (void)out_size;
    const float* x         = (const float*)d_in[0];
    const float* ln1_s     = (const float*)d_in[1];
    const float* ln1_b     = (const float*)d_in[2];
    const float* Wq        = (const float*)d_in[3];
    const float* Wkv       = (const float*)d_in[4];
    const float* bkv       = (const float*)d_in[5];
    const float* Wo        = (const float*)d_in[6];
    const float* bo        = (const float*)d_in[7];
    const float* gamma     = (const float*)d_in[8];
    const float* ln2_s     = (const float*)d_in[9];
    const float* ln2_b     = (const float*)d_in[10];
    const float* W1        = (const float*)d_in[11];
    const float* b1        = (const float*)d_in[12];
    const float* W2        = (const float*)d_in[13];
    const float* b2        = (const float*)d_in[14];
    const float* gamma_mlp = (const float*)d_in[15];
    float* out = (float*)d_out;

    k_cvt<<<96, 256>>>(Wq, Wkv, Wo, W1, W2);
    k1_ln_qkv<<<NTOK / 64, 256>>>(x, ln1_s, ln1_b, bkv);
    k2_attn<<<512 * 4, 128>>>(bkv);
    k3_post<<<NTOK / 64, 128>>>(x, bo, gamma, ln2_s, ln2_b, b1, b2, gamma_mlp, out);
}

// round 7
// speedup vs baseline: 7.6600x; 1.0528x over previous
#include <cuda_runtime.h>
#include <cuda_bf16.h>
#include <math.h>

#define NTOK 65536
#define SCALE 0.17677669529663687f   // 1/sqrt(32), folded into q

// ---------------- device scratch ----------------
// q and o in consumer mma A-fragment order:
//   word[((blk*8 + kc)*32 + lane)*4 + e], blk = token/16, kc = word/8,
//   e: 0=tok(g) low-half, 1=tok(g+8) low, 2=tok(g) high, 3=tok(g+8) high
__device__ unsigned g_qF[NTOK * 64];
__device__ unsigned g_oF[NTOK * 64];
// k/v head-major: word[hh*NTOK*16 + tok*16 + w16]
__device__ unsigned g_kH[4 * NTOK * 16];
__device__ unsigned g_vH[4 * NTOK * 16];
// weights packed in per-lane mma B-fragment order
__device__ unsigned WqkvP[12288];   // N=384, K=64  (KC=4, NT=48)
__device__ unsigned WoP[4096];      // N=64,  K=128 (KC=8, NT=8)
__device__ unsigned W1P[4096];      // N=128, K=64  (KC=4, NT=16)
__device__ unsigned W2P[4096];      // N=64,  K=128 (KC=8, NT=8)

// token index: ((((v*2 + Ti)*256 + n)*4 + tt)*4 + nn)*4 + dd
__device__ __forceinline__ int xoff_of_token(int tok) {
    int dd = tok & 3;
    int nn = (tok >> 2) & 3;
    int tt = (tok >> 4) & 3;
    int n  = (tok >> 6) & 255;
    int Ti = (tok >> 14) & 1;
    int v  = (tok >> 15) & 1;
    return v * 2097152 + (Ti * 4 + tt) * 262144 + (n * 4 + nn) * 256 + dd * 64;
}

__device__ __forceinline__ unsigned pack_bf2(float lo, float hi) {
    unsigned ulo = (unsigned)__bfloat16_as_ushort(__float2bfloat16(lo));
    unsigned uhi = (unsigned)__bfloat16_as_ushort(__float2bfloat16(hi));
    return (uhi << 16) | ulo;
}
__device__ __forceinline__ float bf_lo(unsigned u) {
    return __bfloat162float(__ushort_as_bfloat16((unsigned short)(u & 0xffff)));
}
__device__ __forceinline__ float bf_hi(unsigned u) {
    return __bfloat162float(__ushort_as_bfloat16((unsigned short)(u >> 16)));
}
__device__ __forceinline__ float tanha(float x) {
    float y; asm("tanh.approx.f32 %0, %1;" : "=f"(y) : "f"(x)); return y;
}

__device__ __forceinline__ void mma16816(float c[4], const unsigned a[4], unsigned b0, unsigned b1) {
    asm volatile(
        "mma.sync.aligned.m16n8k16.row.col.f32.bf16.bf16.f32 "
        "{%0,%1,%2,%3}, {%4,%5,%6,%7}, {%8,%9}, {%0,%1,%2,%3};"
        : "+f"(c[0]), "+f"(c[1]), "+f"(c[2]), "+f"(c[3])
        : "r"(a[0]), "r"(a[1]), "r"(a[2]), "r"(a[3]), "r"(b0), "r"(b1));
}
__device__ __forceinline__ void ldsm4(unsigned r[4], const void* p) {
    unsigned addr = (unsigned)__cvta_generic_to_shared(p);
    asm volatile("ldmatrix.sync.aligned.m8n8.x4.shared.b16 {%0,%1,%2,%3}, [%4];"
        : "=r"(r[0]), "=r"(r[1]), "=r"(r[2]), "=r"(r[3]) : "r"(addr));
}
__device__ __forceinline__ void ldsm4t(unsigned r[4], const void* p) {
    unsigned addr = (unsigned)__cvta_generic_to_shared(p);
    asm volatile("ldmatrix.sync.aligned.m8n8.x4.trans.shared.b16 {%0,%1,%2,%3}, [%4];"
        : "=r"(r[0]), "=r"(r[1]), "=r"(r[2]), "=r"(r[3]) : "r"(addr));
}

// ---------------------------------------------------------------------------
// k_cvt: pack all weights into per-lane fragment order
// ---------------------------------------------------------------------------
__global__ void k_cvt(const float* __restrict__ Wq, const float* __restrict__ Wkv,
                      const float* __restrict__ Wo, const float* __restrict__ W1,
                      const float* __restrict__ W2)
{
    int i = blockIdx.x * 256 + threadIdx.x;
    if (i < 12288) {                       // Wqkv: KC=4
        int h = i & 1, kc = (i >> 1) & 3, t = (i >> 3) & 3, g = (i >> 5) & 7, nt = i >> 8;
        int n = nt * 8 + g, k = kc * 16 + 2 * t + 8 * h;
        float v0, v1;
        if (n < 128) { v0 = Wq[k * 128 + n]; v1 = Wq[(k + 1) * 128 + n]; }
        else         { v0 = Wkv[k * 256 + n - 128]; v1 = Wkv[(k + 1) * 256 + n - 128]; }
        WqkvP[i] = pack_bf2(v0, v1);
    } else if (i < 16384) {                // Wo: KC=8
        int j = i - 12288;
        int h = j & 1, kc = (j >> 1) & 7, t = (j >> 4) & 3, g = (j >> 6) & 7, nt = j >> 9;
        int n = nt * 8 + g, k = kc * 16 + 2 * t + 8 * h;
        WoP[j] = pack_bf2(Wo[k * 64 + n], Wo[(k + 1) * 64 + n]);
    } else if (i < 20480) {                // W1: KC=4
        int j = i - 16384;
        int h = j & 1, kc = (j >> 1) & 3, t = (j >> 3) & 3, g = (j >> 5) & 7, nt = j >> 8;
        int n = nt * 8 + g, k = kc * 16 + 2 * t + 8 * h;
        W1P[j] = pack_bf2(W1[k * 128 + n], W1[(k + 1) * 128 + n]);
    } else if (i < 24576) {                // W2: KC=8
        int j = i - 20480;
        int h = j & 1, kc = (j >> 1) & 7, t = (j >> 4) & 3, g = (j >> 6) & 7, nt = j >> 9;
        int n = nt * 8 + g, k = kc * 16 + 2 * t + 8 * h;
        W2P[j] = pack_bf2(W2[k * 64 + n], W2[(k + 1) * 64 + n]);
    }
}

// ---------------------------------------------------------------------------
// k1: LN1 + QKV projection. 64 tokens/CTA, 256 threads (2 Mwarps x 4 Nwarps).
// q written to g_qF fragment layout (SCALE folded); k/v head-major.
// ---------------------------------------------------------------------------
__global__ void __launch_bounds__(256) k1_ln_qkv(
    const float* __restrict__ x,
    const float* __restrict__ ln1_s, const float* __restrict__ ln1_b,
    const float* __restrict__ bkv)
{
    __shared__ unsigned sA[64 * 36];
    const int tid = threadIdx.x;
    const int tokBase = blockIdx.x * 64;

    // --- LN1: 4 lanes per row ---
    {
        int row = tid >> 2, s = tid & 3;
        const float* xr = x + xoff_of_token(tokBase + row);
        float h[16];
        #pragma unroll
        for (int j = 0; j < 4; j++) {
            float4 xv = *(const float4*)(xr + s * 16 + j * 4);
            h[4 * j + 0] = xv.x; h[4 * j + 1] = xv.y; h[4 * j + 2] = xv.z; h[4 * j + 3] = xv.w;
        }
        float a = 0.0f, q2 = 0.0f;
        #pragma unroll
        for (int j = 0; j < 16; j++) { a += h[j]; q2 += h[j] * h[j]; }
        a  += __shfl_xor_sync(0xffffffffu, a, 1);  a  += __shfl_xor_sync(0xffffffffu, a, 2);
        q2 += __shfl_xor_sync(0xffffffffu, q2, 1); q2 += __shfl_xor_sync(0xffffffffu, q2, 2);
        float mean = a * (1.0f / 64.0f);
        float rstd = rsqrtf(q2 * (1.0f / 64.0f) - mean * mean + 1e-5f);
        #pragma unroll
        for (int j = 0; j < 8; j++) {
            int k = s * 16 + 2 * j;
            float h0 = (h[2 * j]     - mean) * rstd * ln1_s[k]     + ln1_b[k];
            float h1 = (h[2 * j + 1] - mean) * rstd * ln1_s[k + 1] + ln1_b[k + 1];
            sA[row * 36 + s * 8 + j] = pack_bf2(h0, h1);
        }
    }
    __syncthreads();

    const int wq = tid >> 5, lane = tid & 31;
    const int mw = wq >> 2, nw = wq & 3;
    const int g = lane >> 2, t = lane & 3;

    unsigned a[2][4][4];
    {
        int rin = (lane & 7) + 8 * ((lane >> 3) & 1);
        int half = lane >> 4;
        #pragma unroll
        for (int mt = 0; mt < 2; mt++) {
            int rowg = mw * 32 + mt * 16 + rin;
            #pragma unroll
            for (int kc = 0; kc < 4; kc++)
                ldsm4(a[mt][kc], &sA[rowg * 36 + kc * 8 + half * 4]);
        }
    }

    const int blk0 = blockIdx.x * 4 + mw * 2;

    #pragma unroll
    for (int nt = 0; nt < 12; nt++) {
        float acc0[4] = {0, 0, 0, 0}, acc1[4] = {0, 0, 0, 0};
        int base = (((nw * 12 + nt) * 8 + g) * 4 + t) * 8;
        uint4 u0 = *(const uint4*)&WqkvP[base];
        uint4 u1 = *(const uint4*)&WqkvP[base + 4];
        mma16816(acc0, a[0][0], u0.x, u0.y);
        mma16816(acc0, a[0][1], u0.z, u0.w);
        mma16816(acc0, a[0][2], u1.x, u1.y);
        mma16816(acc0, a[0][3], u1.z, u1.w);
        mma16816(acc1, a[1][0], u0.x, u0.y);
        mma16816(acc1, a[1][1], u0.z, u0.w);
        mma16816(acc1, a[1][2], u1.x, u1.y);
        mma16816(acc1, a[1][3], u1.z, u1.w);

        int idx = nw * 48 + nt * 4;      // word base (t excluded)
        int w = idx + t;
        int n0 = 2 * idx + 2 * t;
        #pragma unroll
        for (int mt = 0; mt < 2; mt++) {
            float* c = (mt == 0) ? acc0 : acc1;
            int tok0 = tokBase + mw * 32 + mt * 16 + g;
            int tok1 = tok0 + 8;
            if (idx < 64) {            // q -> fragment layout
                int hh = w >> 4, kc2 = (w >> 3) & 1, half = nt & 1;
                int addr = (((blk0 + mt) * 8 + hh * 2 + kc2) * 32 + lane) * 4 + half * 2;
                *(uint2*)&g_qF[addr] = make_uint2(pack_bf2(c[0] * SCALE, c[1] * SCALE),
                                                  pack_bf2(c[2] * SCALE, c[3] * SCALE));
            } else if (idx < 128) {    // k -> head-major
                int w64 = w - 64, hh = w64 >> 4, w16 = w64 & 15;
                float bb0 = bkv[n0 - 128], bb1 = bkv[n0 - 127];
                g_kH[hh * (NTOK * 16) + tok0 * 16 + w16] = pack_bf2(c[0] + bb0, c[1] + bb1);
                g_kH[hh * (NTOK * 16) + tok1 * 16 + w16] = pack_bf2(c[2] + bb0, c[3] + bb1);
            } else {                   // v -> head-major
                int w64 = w - 128, hh = w64 >> 4, w16 = w64 & 15;
                float bb0 = bkv[n0 - 256], bb1 = bkv[n0 - 255];
                g_vH[hh * (NTOK * 16) + tok0 * 16 + w16] = pack_bf2(c[0] + bb0, c[1] + bb1);
                g_vH[hh * (NTOK * 16) + tok1 * 16 + w16] = pack_bf2(c[2] + bb0, c[3] + bb1);
            }
        }
    }
}

// ---------------------------------------------------------------------------
// k2: flash attention, no running max (scores are tiny; exp safe with max=0).
// CTA = (window, head), 2048 CTAs, 128 threads. Whole 192-row KV in smem.
// ---------------------------------------------------------------------------
__global__ void __launch_bounds__(128) k2_attn(const float* __restrict__ bkv)
{
    __shared__ unsigned sK[192 * 20];
    __shared__ unsigned sV[192 * 20];
    __shared__ float kh[32], vh[32];

    const int bid = blockIdx.x;
    const int hh = bid & 3;
    const int w  = bid >> 2;
    const int Ti = w >> 8;
    const int n  = w & 255;
    const int tid = threadIdx.x;
    const int wid = tid >> 5, lane = tid & 31;
    const int g = lane >> 2, t = lane & 3;
    const int lo = (Ti > 0) ? 2 : 0;

    if (tid < 32) {
        kh[tid] = bkv[hh * 32 + tid];
        vh[tid] = bkv[128 + hh * 32 + tid];
    }

    // cooperative whole-window load (head-major -> contiguous runs)
    {
        const uint4* kg4 = (const uint4*)g_kH;
        const uint4* vg4 = (const uint4*)g_vH;
        #pragma unroll
        for (int i = 0; i < 6; i++) {
            int c = tid + 128 * i;
            int row = c >> 2, part = c & 3;
            int rdd = row & 3, rnn = (row >> 2) & 3, rt = row >> 4;
            int tsel = rt % 6, v2 = rt / 6;
            int Tsrc, rtt;
            if (tsel < lo)            { Tsrc = Ti - 1; rtt = 2 + tsel; }
            else if (tsel < lo + 4)   { Tsrc = Ti;     rtt = tsel - lo; }
            else                      { Tsrc = Ti + 1; rtt = tsel - lo - 4; }
            int tokR = ((((v2 * 2 + Tsrc) * 256 + n) * 4 + rtt) * 4 + rnn) * 4 + rdd;
            int src = hh * (NTOK * 4) + tokR * 4 + part;
            *(uint4*)&sK[row * 20 + part * 4] = kg4[src];
            *(uint4*)&sV[row * 20 + part * 4] = vg4[src];
        }
    }

    // q fragments via coalesced LDG.128
    unsigned qa[2][2][4];
    int blkm[2];
    #pragma unroll
    for (int mt = 0; mt < 2; mt++) {
        int r0 = wid * 32 + mt * 16;
        int tt = (r0 >> 4) & 3, v2 = r0 >> 6;
        blkm[mt] = (((v2 * 2 + Ti) * 256 + n) * 4 + tt);
        #pragma unroll
        for (int kc = 0; kc < 2; kc++) {
            uint4 u = *(const uint4*)&g_qF[((blkm[mt] * 8 + hh * 2 + kc) * 32 + lane) * 4];
            qa[mt][kc][0] = u.x; qa[mt][kc][1] = u.y; qa[mt][kc][2] = u.z; qa[mt][kc][3] = u.w;
        }
    }

    float lp0[2] = {0.0f, 0.0f}, lp1[2] = {0.0f, 0.0f};
    float acc[2][4][4];
    #pragma unroll
    for (int mt = 0; mt < 2; mt++)
        #pragma unroll
        for (int ot = 0; ot < 4; ot++)
            #pragma unroll
            for (int e = 0; e < 4; e++) acc[mt][ot][e] = 0.0f;

    __syncthreads();

    const int krow_in = lane & 7;
    const int kcolw   = (lane >> 3) * 4;
    const int vrow_in = ((lane >> 3) & 1) * 8 + (lane & 7);
    const int vcolw   = (lane >> 4) * 4;

    for (int c = 0; c < 12; c++) {
        const int n0 = c * 16;

        unsigned kb[2][4];
        #pragma unroll
        for (int nt = 0; nt < 2; nt++)
            ldsm4(kb[nt], &sK[(n0 + nt * 8 + krow_in) * 20 + kcolw]);

        unsigned vb[2][4];
        #pragma unroll
        for (int op = 0; op < 2; op++)
            ldsm4t(vb[op], &sV[(n0 + vrow_in) * 20 + op * 8 + vcolw]);

        #pragma unroll
        for (int mt = 0; mt < 2; mt++) {
            float s0[4] = {0, 0, 0, 0}, s1[4] = {0, 0, 0, 0};
            mma16816(s0, qa[mt][0], kb[0][0], kb[0][1]);
            mma16816(s0, qa[mt][1], kb[0][2], kb[0][3]);
            mma16816(s1, qa[mt][0], kb[1][0], kb[1][1]);
            mma16816(s1, qa[mt][1], kb[1][2], kb[1][3]);

            float p00 = __expf(s0[0]), p01 = __expf(s0[1]);
            float p10 = __expf(s1[0]), p11 = __expf(s1[1]);
            float q00 = __expf(s0[2]), q01 = __expf(s0[3]);
            float q10 = __expf(s1[2]), q11 = __expf(s1[3]);
            lp0[mt] += (p00 + p01) + (p10 + p11);
            lp1[mt] += (q00 + q01) + (q10 + q11);

            unsigned pa[4];
            pa[0] = pack_bf2(p00, p01);
            pa[1] = pack_bf2(q00, q01);
            pa[2] = pack_bf2(p10, p11);
            pa[3] = pack_bf2(q10, q11);

            mma16816(acc[mt][0], pa, vb[0][0], vb[0][1]);
            mma16816(acc[mt][1], pa, vb[0][2], vb[0][3]);
            mma16816(acc[mt][2], pa, vb[1][0], vb[1][1]);
            mma16816(acc[mt][3], pa, vb[1][2], vb[1][3]);
        }
    }

    // epilogue: halo column (multiplicity 320) + normalize + write oF
    #pragma unroll
    for (int mt = 0; mt < 2; mt++) {
        float hd0 = 0.0f, hd1 = 0.0f;
        #pragma unroll
        for (int kc = 0; kc < 2; kc++) {
            int kb0 = kc * 16 + 2 * t;
            hd0 += bf_lo(qa[mt][kc][0]) * kh[kb0]     + bf_hi(qa[mt][kc][0]) * kh[kb0 + 1];
            hd0 += bf_lo(qa[mt][kc][2]) * kh[kb0 + 8] + bf_hi(qa[mt][kc][2]) * kh[kb0 + 9];
            hd1 += bf_lo(qa[mt][kc][1]) * kh[kb0]     + bf_hi(qa[mt][kc][1]) * kh[kb0 + 1];
            hd1 += bf_lo(qa[mt][kc][3]) * kh[kb0 + 8] + bf_hi(qa[mt][kc][3]) * kh[kb0 + 9];
        }
        hd0 += __shfl_xor_sync(0xffffffffu, hd0, 1);
        hd0 += __shfl_xor_sync(0xffffffffu, hd0, 2);
        hd1 += __shfl_xor_sync(0xffffffffu, hd1, 1);
        hd1 += __shfl_xor_sync(0xffffffffu, hd1, 2);
        float l0 = lp0[mt], l1 = lp1[mt];
        l0 += __shfl_xor_sync(0xffffffffu, l0, 1);
        l0 += __shfl_xor_sync(0xffffffffu, l0, 2);
        l1 += __shfl_xor_sync(0xffffffffu, l1, 1);
        l1 += __shfl_xor_sync(0xffffffffu, l1, 2);
        float ph0 = __expf(hd0) * 320.0f;
        float ph1 = __expf(hd1) * 320.0f;
        float inv0 = 1.0f / (l0 + ph0);
        float inv1 = 1.0f / (l1 + ph1);

        #pragma unroll
        for (int ot = 0; ot < 4; ot++) {
            int c0 = ot * 8 + 2 * t;
            float f0 = (acc[mt][ot][0] + ph0 * vh[c0])     * inv0;
            float f1 = (acc[mt][ot][1] + ph0 * vh[c0 + 1]) * inv0;
            float f2 = (acc[mt][ot][2] + ph1 * vh[c0])     * inv1;
            float f3 = (acc[mt][ot][3] + ph1 * vh[c0 + 1]) * inv1;
            int addr = ((blkm[mt] * 8 + hh * 2 + (ot >> 1)) * 32 + lane) * 4 + (ot & 1) * 2;
            *(uint2*)&g_oF[addr] = make_uint2(pack_bf2(f0, f1), pack_bf2(f2, f3));
        }
    }
}

// ---------------------------------------------------------------------------
// k3: fused Wo+residual+LN2+MLP1+gelu+MLP2+residual.
// tok lives in smem (in-place over the x staging buffer) -> regs <= 128,
// 4 CTAs/SM. All tok accesses are thread-local slots (no extra syncs).
// ---------------------------------------------------------------------------
__global__ void __launch_bounds__(128, 4) k3_post(
    const float* __restrict__ x,
    const float* __restrict__ bo, const float* __restrict__ gamma,
    const float* __restrict__ ln2_s, const float* __restrict__ ln2_b,
    const float* __restrict__ b1, const float* __restrict__ b2,
    const float* __restrict__ gamma_mlp, float* __restrict__ out)
{
    __shared__ float sp[512];
    __shared__ float4 sxF[4 * 264];   // x frags -> tok (in place) -> out (in place)
    const int tid = threadIdx.x;
    for (int i = tid; i < 512; i += 128) {
        float v;
        if (i < 64)       v = bo[i];
        else if (i < 128) v = gamma[i - 64];
        else if (i < 192) v = ln2_s[i - 128];
        else if (i < 256) v = ln2_b[i - 192];
        else if (i < 384) v = b1[i - 256];
        else if (i < 448) v = b2[i - 384];
        else              v = gamma_mlp[i - 448];
        sp[i] = v;
    }
    const float* s_bo = sp;        const float* s_gm = sp + 64;
    const float* s_ls = sp + 128;  const float* s_lb = sp + 192;
    const float* s_b1 = sp + 256;  const float* s_b2 = sp + 384;
    const float* s_gmlp = sp + 448;

    const int R0 = blockIdx.x * 64;
    const int xbase = xoff_of_token(R0);

    // coop coalesced x load -> fragment-order smem
    for (int j = tid; j < 1024; j += 128) {
        int tt = j >> 8, rem = j & 255;
        float4 v = *(const float4*)(x + xbase + tt * 262144 + (rem >> 4) * 64 + (rem & 15) * 4);
        int tk6 = tt * 16 + (rem >> 4);
        int wdst = tk6 >> 4, gg = tk6 & 7, e = (tk6 >> 3) & 1;
        int f0 = (rem & 15) * 4;
        int t0 = (f0 >> 1) & 3, nt = f0 >> 3;
        float2* b2p = (float2*)&sxF[wdst * 264 + nt * 33];
        int li0 = gg * 4 + t0;
        b2p[li0 * 2 + e]       = make_float2(v.x, v.y);
        b2p[(li0 + 1) * 2 + e] = make_float2(v.z, v.w);
    }
    __syncthreads();

    const int wid = tid >> 5, lane = tid & 31;
    const int g = lane >> 2, t = lane & 3;
    const int blk = blockIdx.x * 4 + wid;
    float4* myslot = &sxF[wid * 264 + lane];   // + nt*33

    // ---- GEMM1: upd = o @ Wo ; tok = x + gamma*(upd+bo) -> smem in place,
    //      LN2 sums accumulated on the fly ----
    unsigned ao[8][4];
    #pragma unroll
    for (int kc = 0; kc < 8; kc++) {
        uint4 u = *(const uint4*)&g_oF[((blk * 8 + kc) * 32 + lane) * 4];
        ao[kc][0] = u.x; ao[kc][1] = u.y; ao[kc][2] = u.z; ao[kc][3] = u.w;
    }
    float sum0 = 0.0f, sq0 = 0.0f, sum1 = 0.0f, sq1 = 0.0f;
    #pragma unroll
    for (int nt = 0; nt < 8; nt++) {
        float acc[4] = {0, 0, 0, 0};
        int base = ((nt * 8 + g) * 4 + t) * 16;
        uint4 u0 = *(const uint4*)&WoP[base];
        uint4 u1 = *(const uint4*)&WoP[base + 4];
        uint4 u2 = *(const uint4*)&WoP[base + 8];
        uint4 u3 = *(const uint4*)&WoP[base + 12];
        mma16816(acc, ao[0], u0.x, u0.y);
        mma16816(acc, ao[1], u0.z, u0.w);
        mma16816(acc, ao[2], u1.x, u1.y);
        mma16816(acc, ao[3], u1.z, u1.w);
        mma16816(acc, ao[4], u2.x, u2.y);
        mma16816(acc, ao[5], u2.z, u2.w);
        mma16816(acc, ao[6], u3.x, u3.y);
        mma16816(acc, ao[7], u3.z, u3.w);
        int n0 = nt * 8 + 2 * t;
        float4 xf = myslot[nt * 33];
        float t0v = xf.x + s_gm[n0]     * (acc[0] + s_bo[n0]);
        float t1v = xf.y + s_gm[n0 + 1] * (acc[1] + s_bo[n0 + 1]);
        float t2v = xf.z + s_gm[n0]     * (acc[2] + s_bo[n0]);
        float t3v = xf.w + s_gm[n0 + 1] * (acc[3] + s_bo[n0 + 1]);
        myslot[nt * 33] = make_float4(t0v, t1v, t2v, t3v);
        sum0 += t0v + t1v;  sq0 += t0v * t0v + t1v * t1v;
        sum1 += t2v + t3v;  sq1 += t2v * t2v + t3v * t3v;
    }

    // ---- LN2 stats ----
    sum0 += __shfl_xor_sync(0xffffffffu, sum0, 1); sum0 += __shfl_xor_sync(0xffffffffu, sum0, 2);
    sq0  += __shfl_xor_sync(0xffffffffu, sq0, 1);  sq0  += __shfl_xor_sync(0xffffffffu, sq0, 2);
    sum1 += __shfl_xor_sync(0xffffffffu, sum1, 1); sum1 += __shfl_xor_sync(0xffffffffu, sum1, 2);
    sq1  += __shfl_xor_sync(0xffffffffu, sq1, 1);  sq1  += __shfl_xor_sync(0xffffffffu, sq1, 2);
    float mean0 = sum0 * (1.0f / 64.0f);
    float mean1 = sum1 * (1.0f / 64.0f);
    float rstd0 = rsqrtf(sq0 * (1.0f / 64.0f) - mean0 * mean0 + 1e-5f);
    float rstd1 = rsqrtf(sq1 * (1.0f / 64.0f) - mean1 * mean1 + 1e-5f);

    // ---- h2 A-fragments (re-read tok from smem, thread-local slots) ----
    unsigned ah[4][4];
    #pragma unroll
    for (int kc = 0; kc < 4; kc++) {
        int ta = 2 * kc, tb = 2 * kc + 1;
        int ca = ta * 8 + 2 * t, cb = tb * 8 + 2 * t;
        float4 va = myslot[ta * 33];
        float4 vb = myslot[tb * 33];
        float a0 = (va.x - mean0) * rstd0 * s_ls[ca]     + s_lb[ca];
        float a1 = (va.y - mean0) * rstd0 * s_ls[ca + 1] + s_lb[ca + 1];
        float a2 = (va.z - mean1) * rstd1 * s_ls[ca]     + s_lb[ca];
        float a3 = (va.w - mean1) * rstd1 * s_ls[ca + 1] + s_lb[ca + 1];
        float bb0 = (vb.x - mean0) * rstd0 * s_ls[cb]     + s_lb[cb];
        float bb1 = (vb.y - mean0) * rstd0 * s_ls[cb + 1] + s_lb[cb + 1];
        float bb2 = (vb.z - mean1) * rstd1 * s_ls[cb]     + s_lb[cb];
        float bb3 = (vb.w - mean1) * rstd1 * s_ls[cb + 1] + s_lb[cb + 1];
        ah[kc][0] = pack_bf2(a0, a1);
        ah[kc][1] = pack_bf2(a2, a3);
        ah[kc][2] = pack_bf2(bb0, bb1);
        ah[kc][3] = pack_bf2(bb2, bb3);
    }

    // ---- GEMM2 + gelu + A-frag pack, fused per kc pair ----
    unsigned aa[8][4];
    #pragma unroll
    for (int kc2 = 0; kc2 < 8; kc2++) {
        float accA[4] = {0, 0, 0, 0}, accB[4] = {0, 0, 0, 0};
        int ntA = 2 * kc2, ntB = ntA + 1;
        int baseA = ((ntA * 8 + g) * 4 + t) * 8;
        int baseB = ((ntB * 8 + g) * 4 + t) * 8;
        uint4 a0 = *(const uint4*)&W1P[baseA];
        uint4 a1 = *(const uint4*)&W1P[baseA + 4];
        uint4 b0 = *(const uint4*)&W1P[baseB];
        uint4 b1 = *(const uint4*)&W1P[baseB + 4];
        mma16816(accA, ah[0], a0.x, a0.y);
        mma16816(accA, ah[1], a0.z, a0.w);
        mma16816(accA, ah[2], a1.x, a1.y);
        mma16816(accA, ah[3], a1.z, a1.w);
        mma16816(accB, ah[0], b0.x, b0.y);
        mma16816(accB, ah[1], b0.z, b0.w);
        mma16816(accB, ah[2], b1.x, b1.y);
        mma16816(accB, ah[3], b1.z, b1.w);
        int nA = ntA * 8 + 2 * t, nB = ntB * 8 + 2 * t;
        float gA[4], gB[4];
        #pragma unroll
        for (int e = 0; e < 4; e++) {
            float uu = accA[e] + s_b1[nA + (e & 1)];
            float inner = 0.7978845608028654f * (uu + 0.044715f * uu * uu * uu);
            gA[e] = 0.5f * uu * (1.0f + tanha(inner));
            float vv = accB[e] + s_b1[nB + (e & 1)];
            float inner2 = 0.7978845608028654f * (vv + 0.044715f * vv * vv * vv);
            gB[e] = 0.5f * vv * (1.0f + tanha(inner2));
        }
        aa[kc2][0] = pack_bf2(gA[0], gA[1]);
        aa[kc2][1] = pack_bf2(gA[2], gA[3]);
        aa[kc2][2] = pack_bf2(gB[0], gB[1]);
        aa[kc2][3] = pack_bf2(gB[2], gB[3]);
    }

    // ---- GEMM3 -> out, in place over tok slots ----
    #pragma unroll
    for (int nt = 0; nt < 8; nt++) {
        float acc[4] = {0, 0, 0, 0};
        int base = ((nt * 8 + g) * 4 + t) * 16;
        uint4 u0 = *(const uint4*)&W2P[base];
        uint4 u1 = *(const uint4*)&W2P[base + 4];
        uint4 u2 = *(const uint4*)&W2P[base + 8];
        uint4 u3 = *(const uint4*)&W2P[base + 12];
        mma16816(acc, aa[0], u0.x, u0.y);
        mma16816(acc, aa[1], u0.z, u0.w);
        mma16816(acc, aa[2], u1.x, u1.y);
        mma16816(acc, aa[3], u1.z, u1.w);
        mma16816(acc, aa[4], u2.x, u2.y);
        mma16816(acc, aa[5], u2.z, u2.w);
        mma16816(acc, aa[6], u3.x, u3.y);
        mma16816(acc, aa[7], u3.z, u3.w);
        int n0 = nt * 8 + 2 * t;
        float4 tk = myslot[nt * 33];
        float4 o;
        o.x = tk.x + s_gmlp[n0]     * (acc[0] + s_b2[n0]);
        o.y = tk.y + s_gmlp[n0 + 1] * (acc[1] + s_b2[n0 + 1]);
        o.z = tk.z + s_gmlp[n0]     * (acc[2] + s_b2[n0]);
        o.w = tk.w + s_gmlp[n0 + 1] * (acc[3] + s_b2[n0 + 1]);
        myslot[nt * 33] = o;
    }
    __syncthreads();

    // coop coalesced store
    for (int j = tid; j < 1024; j += 128) {
        int tt = j >> 8, rem = j & 255;
        int tk6 = tt * 16 + (rem >> 4);
        int wsrc = tk6 >> 4, gg = tk6 & 7, e = (tk6 >> 3) & 1;
        int f0 = (rem & 15) * 4;
        int t0 = (f0 >> 1) & 3, nt = f0 >> 3;
        const float2* b2p = (const float2*)&sxF[wsrc * 264 + nt * 33];
        int li0 = gg * 4 + t0;
        float2 va = b2p[li0 * 2 + e];
        float2 vb = b2p[(li0 + 1) * 2 + e];
        *(float4*)(out + xbase + tt * 262144 + (rem >> 4) * 64 + f0) =
            make_float4(va.x, va.y, vb.x, vb.y);
    }
}

// ---------------------------------------------------------------------------
extern "C" void kernel_launch(void* const* d_in, const int* in_sizes, int n_in,
                              void* d_out, int out_size)
{
    (void)in_sizes; (void)n_in; (void)out_size;
    const float* x         = (const float*)d_in[0];
    const float* ln1_s     = (const float*)d_in[1];
    const float* ln1_b     = (const float*)d_in[2];
    const float* Wq        = (const float*)d_in[3];
    const float* Wkv       = (const float*)d_in[4];
    const float* bkv       = (const float*)d_in[5];
    const float* Wo        = (const float*)d_in[6];
    const float* bo        = (const float*)d_in[7];
    const float* gamma     = (const float*)d_in[8];
    const float* ln2_s     = (const float*)d_in[9];
    const float* ln2_b     = (const float*)d_in[10];
    const float* W1        = (const float*)d_in[11];
    const float* b1        = (const float*)d_in[12];
    const float* W2        = (const float*)d_in[13];
    const float* b2        = (const float*)d_in[14];
    const float* gamma_mlp = (const float*)d_in[15];
    float* out = (float*)d_out;

    k_cvt<<<96, 256>>>(Wq, Wkv, Wo, W1, W2);
    k1_ln_qkv<<<NTOK / 64, 256>>>(x, ln1_s, ln1_b, bkv);
    k2_attn<<<512 * 4, 128>>>(bkv);
    k3_post<<<NTOK / 64, 128>>>(x, bo, gamma, ln2_s, ln2_b, b1, b2, gamma_mlp, out);
}

// round 8
// speedup vs baseline: 8.9463x; 1.1679x over previous
#include <cuda_runtime.h>
#include <cuda_bf16.h>
#include <math.h>

#define NTOK 65536
// 1/sqrt(32) * log2(e), folded into q; scores then feed ex2.approx directly
#define SCALEX 0.2550348867f

// ---------------- device scratch ----------------
// q and o in consumer mma A-fragment order:
//   word[((blk*8 + kc)*32 + lane)*4 + e]
__device__ unsigned g_qF[NTOK * 64];
__device__ unsigned g_oF[NTOK * 64];
// k/v head-major: word[hh*NTOK*16 + tok*16 + w16]
__device__ unsigned g_kH[4 * NTOK * 16];
__device__ unsigned g_vH[4 * NTOK * 16];
// weights packed lane-coalesced in mma B-fragment order:
//   word[((nt*J + j4)*32 + lane)*4 + e]  (J = uint4-loads per nt)
__device__ unsigned WqkvP[12288];   // ntq=0..47, J=2
__device__ unsigned WoP[4096];      // nt=0..7,  J=4
__device__ unsigned W1P[4096];      // nt=0..15, J=2
__device__ unsigned W2P[4096];      // nt=0..7,  J=4

// token index: ((((v*2 + Ti)*256 + n)*4 + tt)*4 + nn)*4 + dd
__device__ __forceinline__ int xoff_of_token(int tok) {
    int dd = tok & 3;
    int nn = (tok >> 2) & 3;
    int tt = (tok >> 4) & 3;
    int n  = (tok >> 6) & 255;
    int Ti = (tok >> 14) & 1;
    int v  = (tok >> 15) & 1;
    return v * 2097152 + (Ti * 4 + tt) * 262144 + (n * 4 + nn) * 256 + dd * 64;
}

__device__ __forceinline__ unsigned pack_bf2(float lo, float hi) {
    unsigned ulo = (unsigned)__bfloat16_as_ushort(__float2bfloat16(lo));
    unsigned uhi = (unsigned)__bfloat16_as_ushort(__float2bfloat16(hi));
    return (uhi << 16) | ulo;
}
__device__ __forceinline__ float bf_lo(unsigned u) {
    return __bfloat162float(__ushort_as_bfloat16((unsigned short)(u & 0xffff)));
}
__device__ __forceinline__ float bf_hi(unsigned u) {
    return __bfloat162float(__ushort_as_bfloat16((unsigned short)(u >> 16)));
}
__device__ __forceinline__ float tanha(float x) {
    float y; asm("tanh.approx.f32 %0, %1;" : "=f"(y) : "f"(x)); return y;
}
__device__ __forceinline__ float ex2(float x) {
    float y; asm("ex2.approx.f32 %0, %1;" : "=f"(y) : "f"(x)); return y;
}

__device__ __forceinline__ void mma16816(float c[4], const unsigned a[4], unsigned b0, unsigned b1) {
    asm volatile(
        "mma.sync.aligned.m16n8k16.row.col.f32.bf16.bf16.f32 "
        "{%0,%1,%2,%3}, {%4,%5,%6,%7}, {%8,%9}, {%0,%1,%2,%3};"
        : "+f"(c[0]), "+f"(c[1]), "+f"(c[2]), "+f"(c[3])
        : "r"(a[0]), "r"(a[1]), "r"(a[2]), "r"(a[3]), "r"(b0), "r"(b1));
}
__device__ __forceinline__ void ldsm4(unsigned r[4], const void* p) {
    unsigned addr = (unsigned)__cvta_generic_to_shared(p);
    asm volatile("ldmatrix.sync.aligned.m8n8.x4.shared.b16 {%0,%1,%2,%3}, [%4];"
        : "=r"(r[0]), "=r"(r[1]), "=r"(r[2]), "=r"(r[3]) : "r"(addr));
}
__device__ __forceinline__ void ldsm4t(unsigned r[4], const void* p) {
    unsigned addr = (unsigned)__cvta_generic_to_shared(p);
    asm volatile("ldmatrix.sync.aligned.m8n8.x4.trans.shared.b16 {%0,%1,%2,%3}, [%4];"
        : "=r"(r[0]), "=r"(r[1]), "=r"(r[2]), "=r"(r[3]) : "r"(addr));
}

// ---------------------------------------------------------------------------
// k_cvt: pack all weights into lane-coalesced per-fragment order.
// For entry ((ntX*J + j4)*32 + lane)*4 + e:
//   w = j4*4 + e (word-within-lane), kc = w>>1, h = w&1,
//   g = lane>>2, t = lane&3, n = ntX*8 + g, k = kc*16 + 2t + 8h
//   value = pack(W[k][n], W[k+1][n])
// ---------------------------------------------------------------------------
__global__ void k_cvt(const float* __restrict__ Wq, const float* __restrict__ Wkv,
                      const float* __restrict__ Wo, const float* __restrict__ W1,
                      const float* __restrict__ W2)
{
    int i = blockIdx.x * 256 + threadIdx.x;
    if (i < 12288) {                       // WqkvP: J=2, ntq=0..47
        int e = i & 3, lane = (i >> 2) & 31, rest = i >> 7;
        int j4 = rest & 1, ntq = rest >> 1;
        int g = lane >> 2, t = lane & 3;
        int w = j4 * 4 + e, kc = w >> 1, h = w & 1;
        int n = ntq * 8 + g, k = kc * 16 + 2 * t + 8 * h;
        float v0, v1;
        if (n < 128) { v0 = Wq[k * 128 + n]; v1 = Wq[(k + 1) * 128 + n]; }
        else         { v0 = Wkv[k * 256 + n - 128]; v1 = Wkv[(k + 1) * 256 + n - 128]; }
        WqkvP[i] = pack_bf2(v0, v1);
    } else if (i < 16384) {                // WoP: J=4, nt=0..7
        int j = i - 12288;
        int e = j & 3, lane = (j >> 2) & 31, rest = j >> 7;
        int j4 = rest & 3, nt = rest >> 2;
        int g = lane >> 2, t = lane & 3;
        int w = j4 * 4 + e, kc = w >> 1, h = w & 1;
        int n = nt * 8 + g, k = kc * 16 + 2 * t + 8 * h;
        WoP[j] = pack_bf2(Wo[k * 64 + n], Wo[(k + 1) * 64 + n]);
    } else if (i < 20480) {                // W1P: J=2, nt=0..15
        int j = i - 16384;
        int e = j & 3, lane = (j >> 2) & 31, rest = j >> 7;
        int j4 = rest & 1, nt = rest >> 1;
        int g = lane >> 2, t = lane & 3;
        int w = j4 * 4 + e, kc = w >> 1, h = w & 1;
        int n = nt * 8 + g, k = kc * 16 + 2 * t + 8 * h;
        W1P[j] = pack_bf2(W1[k * 128 + n], W1[(k + 1) * 128 + n]);
    } else if (i < 24576) {                // W2P: J=4, nt=0..7
        int j = i - 20480;
        int e = j & 3, lane = (j >> 2) & 31, rest = j >> 7;
        int j4 = rest & 3, nt = rest >> 2;
        int g = lane >> 2, t = lane & 3;
        int w = j4 * 4 + e, kc = w >> 1, h = w & 1;
        int n = nt * 8 + g, k = kc * 16 + 2 * t + 8 * h;
        W2P[j] = pack_bf2(W2[k * 64 + n], W2[(k + 1) * 64 + n]);
    }
}

// ---------------------------------------------------------------------------
// k1: LN1 + QKV projection. 64 tokens/CTA, 256 threads (2 Mwarps x 4 Nwarps).
// q written to g_qF fragment layout (SCALEX folded); k/v head-major.
// ---------------------------------------------------------------------------
__global__ void __launch_bounds__(256) k1_ln_qkv(
    const float* __restrict__ x,
    const float* __restrict__ ln1_s, const float* __restrict__ ln1_b,
    const float* __restrict__ bkv)
{
    __shared__ unsigned sA[64 * 36];
    const int tid = threadIdx.x;
    const int tokBase = blockIdx.x * 64;

    // --- LN1: 4 lanes per row ---
    {
        int row = tid >> 2, s = tid & 3;
        const float* xr = x + xoff_of_token(tokBase + row);
        float h[16];
        #pragma unroll
        for (int j = 0; j < 4; j++) {
            float4 xv = *(const float4*)(xr + s * 16 + j * 4);
            h[4 * j + 0] = xv.x; h[4 * j + 1] = xv.y; h[4 * j + 2] = xv.z; h[4 * j + 3] = xv.w;
        }
        float a = 0.0f, q2 = 0.0f;
        #pragma unroll
        for (int j = 0; j < 16; j++) { a += h[j]; q2 += h[j] * h[j]; }
        a  += __shfl_xor_sync(0xffffffffu, a, 1);  a  += __shfl_xor_sync(0xffffffffu, a, 2);
        q2 += __shfl_xor_sync(0xffffffffu, q2, 1); q2 += __shfl_xor_sync(0xffffffffu, q2, 2);
        float mean = a * (1.0f / 64.0f);
        float rstd = rsqrtf(q2 * (1.0f / 64.0f) - mean * mean + 1e-5f);
        #pragma unroll
        for (int j = 0; j < 8; j++) {
            int k = s * 16 + 2 * j;
            float h0 = (h[2 * j]     - mean) * rstd * ln1_s[k]     + ln1_b[k];
            float h1 = (h[2 * j + 1] - mean) * rstd * ln1_s[k + 1] + ln1_b[k + 1];
            sA[row * 36 + s * 8 + j] = pack_bf2(h0, h1);
        }
    }
    __syncthreads();

    const int wq = tid >> 5, lane = tid & 31;
    const int mw = wq >> 2, nw = wq & 3;
    const int g = lane >> 2, t = lane & 3;

    unsigned a[2][4][4];
    {
        int rin = (lane & 7) + 8 * ((lane >> 3) & 1);
        int half = lane >> 4;
        #pragma unroll
        for (int mt = 0; mt < 2; mt++) {
            int rowg = mw * 32 + mt * 16 + rin;
            #pragma unroll
            for (int kc = 0; kc < 4; kc++)
                ldsm4(a[mt][kc], &sA[rowg * 36 + kc * 8 + half * 4]);
        }
    }

    const int blk0 = blockIdx.x * 4 + mw * 2;

    #pragma unroll
    for (int nt = 0; nt < 12; nt++) {
        float acc0[4] = {0, 0, 0, 0}, acc1[4] = {0, 0, 0, 0};
        int ntq = nw * 12 + nt;
        uint4 u0 = *(const uint4*)&WqkvP[(ntq * 2 + 0) * 128 + lane * 4];
        uint4 u1 = *(const uint4*)&WqkvP[(ntq * 2 + 1) * 128 + lane * 4];
        mma16816(acc0, a[0][0], u0.x, u0.y);
        mma16816(acc0, a[0][1], u0.z, u0.w);
        mma16816(acc0, a[0][2], u1.x, u1.y);
        mma16816(acc0, a[0][3], u1.z, u1.w);
        mma16816(acc1, a[1][0], u0.x, u0.y);
        mma16816(acc1, a[1][1], u0.z, u0.w);
        mma16816(acc1, a[1][2], u1.x, u1.y);
        mma16816(acc1, a[1][3], u1.z, u1.w);

        int idx = nw * 48 + nt * 4;      // word base (t excluded)
        int w = idx + t;
        int n0 = 2 * idx + 2 * t;
        #pragma unroll
        for (int mt = 0; mt < 2; mt++) {
            float* c = (mt == 0) ? acc0 : acc1;
            int tok0 = tokBase + mw * 32 + mt * 16 + g;
            int tok1 = tok0 + 8;
            if (idx < 64) {            // q -> fragment layout
                int hh = w >> 4, kc2 = (w >> 3) & 1, half = nt & 1;
                int addr = (((blk0 + mt) * 8 + hh * 2 + kc2) * 32 + lane) * 4 + half * 2;
                *(uint2*)&g_qF[addr] = make_uint2(pack_bf2(c[0] * SCALEX, c[1] * SCALEX),
                                                  pack_bf2(c[2] * SCALEX, c[3] * SCALEX));
            } else if (idx < 128) {    // k -> head-major
                int w64 = w - 64, hh = w64 >> 4, w16 = w64 & 15;
                float bb0 = bkv[n0 - 128], bb1 = bkv[n0 - 127];
                g_kH[hh * (NTOK * 16) + tok0 * 16 + w16] = pack_bf2(c[0] + bb0, c[1] + bb1);
                g_kH[hh * (NTOK * 16) + tok1 * 16 + w16] = pack_bf2(c[2] + bb0, c[3] + bb1);
            } else {                   // v -> head-major
                int w64 = w - 128, hh = w64 >> 4, w16 = w64 & 15;
                float bb0 = bkv[n0 - 256], bb1 = bkv[n0 - 255];
                g_vH[hh * (NTOK * 16) + tok0 * 16 + w16] = pack_bf2(c[0] + bb0, c[1] + bb1);
                g_vH[hh * (NTOK * 16) + tok1 * 16 + w16] = pack_bf2(c[2] + bb0, c[3] + bb1);
            }
        }
    }
}

// ---------------------------------------------------------------------------
// k2: flash attention, no running max (scores tiny; ex2 safe with max=0).
// CTA = (window, head), 2048 CTAs, 128 threads. Whole 192-row KV in smem.
// ---------------------------------------------------------------------------
__global__ void __launch_bounds__(128) k2_attn(const float* __restrict__ bkv)
{
    __shared__ unsigned sK[192 * 20];
    __shared__ unsigned sV[192 * 20];
    __shared__ float kh[32], vh[32];

    const int bid = blockIdx.x;
    const int hh = bid & 3;
    const int w  = bid >> 2;
    const int Ti = w >> 8;
    const int n  = w & 255;
    const int tid = threadIdx.x;
    const int wid = tid >> 5, lane = tid & 31;
    const int g = lane >> 2, t = lane & 3;
    const int lo = (Ti > 0) ? 2 : 0;

    if (tid < 32) {
        kh[tid] = bkv[hh * 32 + tid];
        vh[tid] = bkv[128 + hh * 32 + tid];
    }

    // cooperative whole-window load (head-major -> contiguous runs)
    {
        const uint4* kg4 = (const uint4*)g_kH;
        const uint4* vg4 = (const uint4*)g_vH;
        #pragma unroll
        for (int i = 0; i < 6; i++) {
            int c = tid + 128 * i;
            int row = c >> 2, part = c & 3;
            int rdd = row & 3, rnn = (row >> 2) & 3, rt = row >> 4;
            int tsel = rt % 6, v2 = rt / 6;
            int Tsrc, rtt;
            if (tsel < lo)            { Tsrc = Ti - 1; rtt = 2 + tsel; }
            else if (tsel < lo + 4)   { Tsrc = Ti;     rtt = tsel - lo; }
            else                      { Tsrc = Ti + 1; rtt = tsel - lo - 4; }
            int tokR = ((((v2 * 2 + Tsrc) * 256 + n) * 4 + rtt) * 4 + rnn) * 4 + rdd;
            int src = hh * (NTOK * 4) + tokR * 4 + part;
            *(uint4*)&sK[row * 20 + part * 4] = kg4[src];
            *(uint4*)&sV[row * 20 + part * 4] = vg4[src];
        }
    }

    // q fragments via coalesced LDG.128 (SCALEX folded)
    unsigned qa[2][2][4];
    int blkm[2];
    #pragma unroll
    for (int mt = 0; mt < 2; mt++) {
        int r0 = wid * 32 + mt * 16;
        int tt = (r0 >> 4) & 3, v2 = r0 >> 6;
        blkm[mt] = (((v2 * 2 + Ti) * 256 + n) * 4 + tt);
        #pragma unroll
        for (int kc = 0; kc < 2; kc++) {
            uint4 u = *(const uint4*)&g_qF[((blkm[mt] * 8 + hh * 2 + kc) * 32 + lane) * 4];
            qa[mt][kc][0] = u.x; qa[mt][kc][1] = u.y; qa[mt][kc][2] = u.z; qa[mt][kc][3] = u.w;
        }
    }

    float lp0[2] = {0.0f, 0.0f}, lp1[2] = {0.0f, 0.0f};
    float acc[2][4][4];
    #pragma unroll
    for (int mt = 0; mt < 2; mt++)
        #pragma unroll
        for (int ot = 0; ot < 4; ot++)
            #pragma unroll
            for (int e = 0; e < 4; e++) acc[mt][ot][e] = 0.0f;

    __syncthreads();

    const int krow_in = lane & 7;
    const int kcolw   = (lane >> 3) * 4;
    const int vrow_in = ((lane >> 3) & 1) * 8 + (lane & 7);
    const int vcolw   = (lane >> 4) * 4;

    for (int c = 0; c < 12; c++) {
        const int n0 = c * 16;

        unsigned kb[2][4];
        #pragma unroll
        for (int nt = 0; nt < 2; nt++)
            ldsm4(kb[nt], &sK[(n0 + nt * 8 + krow_in) * 20 + kcolw]);

        unsigned vb[2][4];
        #pragma unroll
        for (int op = 0; op < 2; op++)
            ldsm4t(vb[op], &sV[(n0 + vrow_in) * 20 + op * 8 + vcolw]);

        #pragma unroll
        for (int mt = 0; mt < 2; mt++) {
            float s0[4] = {0, 0, 0, 0}, s1[4] = {0, 0, 0, 0};
            mma16816(s0, qa[mt][0], kb[0][0], kb[0][1]);
            mma16816(s0, qa[mt][1], kb[0][2], kb[0][3]);
            mma16816(s1, qa[mt][0], kb[1][0], kb[1][1]);
            mma16816(s1, qa[mt][1], kb[1][2], kb[1][3]);

            float p00 = ex2(s0[0]), p01 = ex2(s0[1]);
            float p10 = ex2(s1[0]), p11 = ex2(s1[1]);
            float q00 = ex2(s0[2]), q01 = ex2(s0[3]);
            float q10 = ex2(s1[2]), q11 = ex2(s1[3]);
            lp0[mt] += (p00 + p01) + (p10 + p11);
            lp1[mt] += (q00 + q01) + (q10 + q11);

            unsigned pa[4];
            pa[0] = pack_bf2(p00, p01);
            pa[1] = pack_bf2(q00, q01);
            pa[2] = pack_bf2(p10, p11);
            pa[3] = pack_bf2(q10, q11);

            mma16816(acc[mt][0], pa, vb[0][0], vb[0][1]);
            mma16816(acc[mt][1], pa, vb[0][2], vb[0][3]);
            mma16816(acc[mt][2], pa, vb[1][0], vb[1][1]);
            mma16816(acc[mt][3], pa, vb[1][2], vb[1][3]);
        }
    }

    // epilogue: halo column (multiplicity 320) + normalize + write oF
    #pragma unroll
    for (int mt = 0; mt < 2; mt++) {
        float hd0 = 0.0f, hd1 = 0.0f;
        #pragma unroll
        for (int kc = 0; kc < 2; kc++) {
            int kb0 = kc * 16 + 2 * t;
            hd0 += bf_lo(qa[mt][kc][0]) * kh[kb0]     + bf_hi(qa[mt][kc][0]) * kh[kb0 + 1];
            hd0 += bf_lo(qa[mt][kc][2]) * kh[kb0 + 8] + bf_hi(qa[mt][kc][2]) * kh[kb0 + 9];
            hd1 += bf_lo(qa[mt][kc][1]) * kh[kb0]     + bf_hi(qa[mt][kc][1]) * kh[kb0 + 1];
            hd1 += bf_lo(qa[mt][kc][3]) * kh[kb0 + 8] + bf_hi(qa[mt][kc][3]) * kh[kb0 + 9];
        }
        hd0 += __shfl_xor_sync(0xffffffffu, hd0, 1);
        hd0 += __shfl_xor_sync(0xffffffffu, hd0, 2);
        hd1 += __shfl_xor_sync(0xffffffffu, hd1, 1);
        hd1 += __shfl_xor_sync(0xffffffffu, hd1, 2);
        float l0 = lp0[mt], l1 = lp1[mt];
        l0 += __shfl_xor_sync(0xffffffffu, l0, 1);
        l0 += __shfl_xor_sync(0xffffffffu, l0, 2);
        l1 += __shfl_xor_sync(0xffffffffu, l1, 1);
        l1 += __shfl_xor_sync(0xffffffffu, l1, 2);
        float ph0 = ex2(hd0) * 320.0f;
        float ph1 = ex2(hd1) * 320.0f;
        float inv0 = 1.0f / (l0 + ph0);
        float inv1 = 1.0f / (l1 + ph1);

        #pragma unroll
        for (int ot = 0; ot < 4; ot++) {
            int c0 = ot * 8 + 2 * t;
            float f0 = (acc[mt][ot][0] + ph0 * vh[c0])     * inv0;
            float f1 = (acc[mt][ot][1] + ph0 * vh[c0 + 1]) * inv0;
            float f2 = (acc[mt][ot][2] + ph1 * vh[c0])     * inv1;
            float f3 = (acc[mt][ot][3] + ph1 * vh[c0 + 1]) * inv1;
            int addr = ((blkm[mt] * 8 + hh * 2 + (ot >> 1)) * 32 + lane) * 4 + (ot & 1) * 2;
            *(uint2*)&g_oF[addr] = make_uint2(pack_bf2(f0, f1), pack_bf2(f2, f3));
        }
    }
}

// ---------------------------------------------------------------------------
// k3: fused Wo+residual+LN2+MLP1+gelu+MLP2+residual.
// tok in smem (in place over x staging), lane-coalesced weight loads,
// split accumulator chains in GEMM1/GEMM3.
// ---------------------------------------------------------------------------
__global__ void __launch_bounds__(128, 4) k3_post(
    const float* __restrict__ x,
    const float* __restrict__ bo, const float* __restrict__ gamma,
    const float* __restrict__ ln2_s, const float* __restrict__ ln2_b,
    const float* __restrict__ b1, const float* __restrict__ b2,
    const float* __restrict__ gamma_mlp, float* __restrict__ out)
{
    __shared__ float sp[512];
    __shared__ float4 sxF[4 * 264];   // x frags -> tok (in place) -> out (in place)
    const int tid = threadIdx.x;
    for (int i = tid; i < 512; i += 128) {
        float v;
        if (i < 64)       v = bo[i];
        else if (i < 128) v = gamma[i - 64];
        else if (i < 192) v = ln2_s[i - 128];
        else if (i < 256) v = ln2_b[i - 192];
        else if (i < 384) v = b1[i - 256];
        else if (i < 448) v = b2[i - 384];
        else              v = gamma_mlp[i - 448];
        sp[i] = v;
    }
    const float* s_bo = sp;        const float* s_gm = sp + 64;
    const float* s_ls = sp + 128;  const float* s_lb = sp + 192;
    const float* s_b1 = sp + 256;  const float* s_b2 = sp + 384;
    const float* s_gmlp = sp + 448;

    const int R0 = blockIdx.x * 64;
    const int xbase = xoff_of_token(R0);

    // coop coalesced x load -> fragment-order smem
    for (int j = tid; j < 1024; j += 128) {
        int tt = j >> 8, rem = j & 255;
        float4 v = *(const float4*)(x + xbase + tt * 262144 + (rem >> 4) * 64 + (rem & 15) * 4);
        int tk6 = tt * 16 + (rem >> 4);
        int wdst = tk6 >> 4, gg = tk6 & 7, e = (tk6 >> 3) & 1;
        int f0 = (rem & 15) * 4;
        int t0 = (f0 >> 1) & 3, nt = f0 >> 3;
        float2* b2p = (float2*)&sxF[wdst * 264 + nt * 33];
        int li0 = gg * 4 + t0;
        b2p[li0 * 2 + e]       = make_float2(v.x, v.y);
        b2p[(li0 + 1) * 2 + e] = make_float2(v.z, v.w);
    }
    __syncthreads();

    const int wid = tid >> 5, lane = tid & 31;
    const int g = lane >> 2, t = lane & 3;
    const int blk = blockIdx.x * 4 + wid;
    float4* myslot = &sxF[wid * 264 + lane];   // + nt*33

    // ---- GEMM1: upd = o @ Wo ; tok = x + gamma*(upd+bo) -> smem in place ----
    unsigned ao[8][4];
    #pragma unroll
    for (int kc = 0; kc < 8; kc++) {
        uint4 u = *(const uint4*)&g_oF[((blk * 8 + kc) * 32 + lane) * 4];
        ao[kc][0] = u.x; ao[kc][1] = u.y; ao[kc][2] = u.z; ao[kc][3] = u.w;
    }
    float sum0 = 0.0f, sq0 = 0.0f, sum1 = 0.0f, sq1 = 0.0f;
    #pragma unroll
    for (int nt = 0; nt < 8; nt++) {
        float acca[4] = {0, 0, 0, 0}, accb[4] = {0, 0, 0, 0};
        uint4 u0 = *(const uint4*)&WoP[(nt * 4 + 0) * 128 + lane * 4];
        uint4 u1 = *(const uint4*)&WoP[(nt * 4 + 1) * 128 + lane * 4];
        uint4 u2 = *(const uint4*)&WoP[(nt * 4 + 2) * 128 + lane * 4];
        uint4 u3 = *(const uint4*)&WoP[(nt * 4 + 3) * 128 + lane * 4];
        mma16816(acca, ao[0], u0.x, u0.y);
        mma16816(acca, ao[1], u0.z, u0.w);
        mma16816(acca, ao[2], u1.x, u1.y);
        mma16816(acca, ao[3], u1.z, u1.w);
        mma16816(accb, ao[4], u2.x, u2.y);
        mma16816(accb, ao[5], u2.z, u2.w);
        mma16816(accb, ao[6], u3.x, u3.y);
        mma16816(accb, ao[7], u3.z, u3.w);
        int n0 = nt * 8 + 2 * t;
        float4 xf = myslot[nt * 33];
        float t0v = xf.x + s_gm[n0]     * ((acca[0] + accb[0]) + s_bo[n0]);
        float t1v = xf.y + s_gm[n0 + 1] * ((acca[1] + accb[1]) + s_bo[n0 + 1]);
        float t2v = xf.z + s_gm[n0]     * ((acca[2] + accb[2]) + s_bo[n0]);
        float t3v = xf.w + s_gm[n0 + 1] * ((acca[3] + accb[3]) + s_bo[n0 + 1]);
        myslot[nt * 33] = make_float4(t0v, t1v, t2v, t3v);
        sum0 += t0v + t1v;  sq0 += t0v * t0v + t1v * t1v;
        sum1 += t2v + t3v;  sq1 += t2v * t2v + t3v * t3v;
    }

    // ---- LN2 stats ----
    sum0 += __shfl_xor_sync(0xffffffffu, sum0, 1); sum0 += __shfl_xor_sync(0xffffffffu, sum0, 2);
    sq0  += __shfl_xor_sync(0xffffffffu, sq0, 1);  sq0  += __shfl_xor_sync(0xffffffffu, sq0, 2);
    sum1 += __shfl_xor_sync(0xffffffffu, sum1, 1); sum1 += __shfl_xor_sync(0xffffffffu, sum1, 2);
    sq1  += __shfl_xor_sync(0xffffffffu, sq1, 1);  sq1  += __shfl_xor_sync(0xffffffffu, sq1, 2);
    float mean0 = sum0 * (1.0f / 64.0f);
    float mean1 = sum1 * (1.0f / 64.0f);
    float rstd0 = rsqrtf(sq0 * (1.0f / 64.0f) - mean0 * mean0 + 1e-5f);
    float rstd1 = rsqrtf(sq1 * (1.0f / 64.0f) - mean1 * mean1 + 1e-5f);

    // ---- h2 A-fragments (re-read tok from smem, thread-local slots) ----
    unsigned ah[4][4];
    #pragma unroll
    for (int kc = 0; kc < 4; kc++) {
        int ta = 2 * kc, tb = 2 * kc + 1;
        int ca = ta * 8 + 2 * t, cb = tb * 8 + 2 * t;
        float4 va = myslot[ta * 33];
        float4 vb = myslot[tb * 33];
        float a0 = (va.x - mean0) * rstd0 * s_ls[ca]     + s_lb[ca];
        float a1 = (va.y - mean0) * rstd0 * s_ls[ca + 1] + s_lb[ca + 1];
        float a2 = (va.z - mean1) * rstd1 * s_ls[ca]     + s_lb[ca];
        float a3 = (va.w - mean1) * rstd1 * s_ls[ca + 1] + s_lb[ca + 1];
        float bb0 = (vb.x - mean0) * rstd0 * s_ls[cb]     + s_lb[cb];
        float bb1 = (vb.y - mean0) * rstd0 * s_ls[cb + 1] + s_lb[cb + 1];
        float bb2 = (vb.z - mean1) * rstd1 * s_ls[cb]     + s_lb[cb];
        float bb3 = (vb.w - mean1) * rstd1 * s_ls[cb + 1] + s_lb[cb + 1];
        ah[kc][0] = pack_bf2(a0, a1);
        ah[kc][1] = pack_bf2(a2, a3);
        ah[kc][2] = pack_bf2(bb0, bb1);
        ah[kc][3] = pack_bf2(bb2, bb3);
    }

    // ---- GEMM2 + gelu + A-frag pack, fused per kc pair ----
    unsigned aa[8][4];
    #pragma unroll
    for (int kc2 = 0; kc2 < 8; kc2++) {
        float accA[4] = {0, 0, 0, 0}, accB[4] = {0, 0, 0, 0};
        int ntA = 2 * kc2, ntB = ntA + 1;
        uint4 a0 = *(const uint4*)&W1P[(ntA * 2 + 0) * 128 + lane * 4];
        uint4 a1 = *(const uint4*)&W1P[(ntA * 2 + 1) * 128 + lane * 4];
        uint4 b0 = *(const uint4*)&W1P[(ntB * 2 + 0) * 128 + lane * 4];
        uint4 b1 = *(const uint4*)&W1P[(ntB * 2 + 1) * 128 + lane * 4];
        mma16816(accA, ah[0], a0.x, a0.y);
        mma16816(accA, ah[1], a0.z, a0.w);
        mma16816(accA, ah[2], a1.x, a1.y);
        mma16816(accA, ah[3], a1.z, a1.w);
        mma16816(accB, ah[0], b0.x, b0.y);
        mma16816(accB, ah[1], b0.z, b0.w);
        mma16816(accB, ah[2], b1.x, b1.y);
        mma16816(accB, ah[3], b1.z, b1.w);
        int nA = ntA * 8 + 2 * t, nB = ntB * 8 + 2 * t;
        float gA[4], gB[4];
        #pragma unroll
        for (int e = 0; e < 4; e++) {
            float uu = accA[e] + s_b1[nA + (e & 1)];
            float inner = 0.7978845608028654f * (uu + 0.044715f * uu * uu * uu);
            gA[e] = 0.5f * uu * (1.0f + tanha(inner));
            float vv = accB[e] + s_b1[nB + (e & 1)];
            float inner2 = 0.7978845608028654f * (vv + 0.044715f * vv * vv * vv);
            gB[e] = 0.5f * vv * (1.0f + tanha(inner2));
        }
        aa[kc2][0] = pack_bf2(gA[0], gA[1]);
        aa[kc2][1] = pack_bf2(gA[2], gA[3]);
        aa[kc2][2] = pack_bf2(gB[0], gB[1]);
        aa[kc2][3] = pack_bf2(gB[2], gB[3]);
    }

    // ---- GEMM3 -> out, in place over tok slots ----
    #pragma unroll
    for (int nt = 0; nt < 8; nt++) {
        float acca[4] = {0, 0, 0, 0}, accb[4] = {0, 0, 0, 0};
        uint4 u0 = *(const uint4*)&W2P[(nt * 4 + 0) * 128 + lane * 4];
        uint4 u1 = *(const uint4*)&W2P[(nt * 4 + 1) * 128 + lane * 4];
        uint4 u2 = *(const uint4*)&W2P[(nt * 4 + 2) * 128 + lane * 4];
        uint4 u3 = *(const uint4*)&W2P[(nt * 4 + 3) * 128 + lane * 4];
        mma16816(acca, aa[0], u0.x, u0.y);
        mma16816(acca, aa[1], u0.z, u0.w);
        mma16816(acca, aa[2], u1.x, u1.y);
        mma16816(acca, aa[3], u1.z, u1.w);
        mma16816(accb, aa[4], u2.x, u2.y);
        mma16816(accb, aa[5], u2.z, u2.w);
        mma16816(accb, aa[6], u3.x, u3.y);
        mma16816(accb, aa[7], u3.z, u3.w);
        int n0 = nt * 8 + 2 * t;
        float4 tk = myslot[nt * 33];
        float4 o;
        o.x = tk.x + s_gmlp[n0]     * ((acca[0] + accb[0]) + s_b2[n0]);
        o.y = tk.y + s_gmlp[n0 + 1] * ((acca[1] + accb[1]) + s_b2[n0 + 1]);
        o.z = tk.z + s_gmlp[n0]     * ((acca[2] + accb[2]) + s_b2[n0]);
        o.w = tk.w + s_gmlp[n0 + 1] * ((acca[3] + accb[3]) + s_b2[n0 + 1]);
        myslot[nt * 33] = o;
    }
    __syncthreads();

    // coop coalesced store
    for (int j = tid; j < 1024; j += 128) {
        int tt = j >> 8, rem = j & 255;
        int tk6 = tt * 16 + (rem >> 4);
        int wsrc = tk6 >> 4, gg = tk6 & 7, e = (tk6 >> 3) & 1;
        int f0 = (rem & 15) * 4;
        int t0 = (f0 >> 1) & 3, nt = f0 >> 3;
        const float2* b2p = (const float2*)&sxF[wsrc * 264 + nt * 33];
        int li0 = gg * 4 + t0;
        float2 va = b2p[li0 * 2 + e];
        float2 vb = b2p[(li0 + 1) * 2 + e];
        *(float4*)(out + xbase + tt * 262144 + (rem >> 4) * 64 + f0) =
            make_float4(va.x, va.y, vb.x, vb.y);
    }
}

// ---------------------------------------------------------------------------
extern "C" void kernel_launch(void* const* d_in, const int* in_sizes, int n_in,
                              void* d_out, int out_size)
{
    (void)in_sizes; (void)n_in; (void)out_size;
    const float* x         = (const float*)d_in[0];
    const float* ln1_s     = (const float*)d_in[1];
    const float* ln1_b     = (const float*)d_in[2];
    const float* Wq        = (const float*)d_in[3];
    const float* Wkv       = (const float*)d_in[4];
    const float* bkv       = (const float*)d_in[5];
    const float* Wo        = (const float*)d_in[6];
    const float* bo        = (const float*)d_in[7];
    const float* gamma     = (const float*)d_in[8];
    const float* ln2_s     = (const float*)d_in[9];
    const float* ln2_b     = (const float*)d_in[10];
    const float* W1        = (const float*)d_in[11];
    const float* b1        = (const float*)d_in[12];
    const float* W2        = (const float*)d_in[13];
    const float* b2        = (const float*)d_in[14];
    const float* gamma_mlp = (const float*)d_in[15];
    float* out = (float*)d_out;

    k_cvt<<<96, 256>>>(Wq, Wkv, Wo, W1, W2);
    k1_ln_qkv<<<NTOK / 64, 256>>>(x, ln1_s, ln1_b, bkv);
    k2_attn<<<512 * 4, 128>>>(bkv);
    k3_post<<<NTOK / 64, 128>>>(x, bo, gamma, ln2_s, ln2_b, b1, b2, gamma_mlp, out);
}